// round 11
// baseline (speedup 1.0000x reference)
#include <cuda_runtime.h>
#include <cstdint>

#define H_HEADS 8
#define D_IN 64
#define D_H 32
#define B_SZ 32
#define N_NODES 512
#define NB 64                      /* es buckets */

typedef unsigned long long ull;

// Scratch: h[h][b][n][k]; attention overwrites each slice in place with the
// per-head aggregated messages; gru averages heads.
__device__ float g_h[H_HEADS * B_SZ * N_NODES * D_H];    // 16 MB

__device__ __forceinline__ ull pack2(float x) {
    ull r; asm("mov.b64 %0, {%1, %1};" : "=l"(r) : "f"(x)); return r;
}
__device__ __forceinline__ void ffma2(ull& acc, ull a, ull b) {
    asm("fma.rn.f32x2 %0, %1, %2, %0;" : "+l"(acc) : "l"(a), "l"(b));
}
__device__ __forceinline__ float lo32(ull v) {
    return __uint_as_float((unsigned)(v & 0xffffffffull));
}
__device__ __forceinline__ float hi32(ull v) {
    return __uint_as_float((unsigned)(v >> 32));
}
__device__ __forceinline__ float ex2f(float t) {
    float p; asm("ex2.approx.f32 %0, %1;" : "=f"(p) : "f"(t)); return p;
}

#define L2E 1.4426950408889634f
#define C02 0.28853900817779268f   /* 0.2 * log2(e) */

// ---------------------------------------------------------------------------
// Kernel 1: h[h,b,n,k] = sum_d inputs[b,n,d] * linear[h,d,k]
// grid = H*B*4 (128-row segments), 256 threads (R2 config: best measured).
// Thread = 4 rows x 4 cols, f32x2 packed accumulation.
// ---------------------------------------------------------------------------
__global__ void __launch_bounds__(256) proj_kernel(const float* __restrict__ inputs,
                                                   const float* __restrict__ linear) {
    const int blk = blockIdx.x;
    const int hb = blk >> 2;
    const int seg = blk & 3;
    const int h = hb >> 5;
    const int b = hb & 31;

    __shared__ __align__(16) float Wsm[D_IN * D_H];   // 8 KB
    __shared__ __align__(16) float xsm[128 * D_IN];   // 32 KB

    {
        const float4* W4 = (const float4*)(linear + h * D_IN * D_H);
        float4* Ws4 = (float4*)Wsm;
        for (int i = threadIdx.x; i < D_IN * D_H / 4; i += 256) Ws4[i] = W4[i];
        const float4* x4 = (const float4*)(inputs +
                           ((size_t)b * N_NODES + seg * 128) * D_IN);
        float4* xs4 = (float4*)xsm;
        for (int i = threadIdx.x; i < 128 * D_IN / 4; i += 256) xs4[i] = x4[i];
    }
    __syncthreads();

    const int k4 = threadIdx.x & 7;        // 16B column chunk (4 cols)
    const int r0 = (threadIdx.x >> 3) * 4; // local row base (0..124)

    ull acc[4][2];
#pragma unroll
    for (int ri = 0; ri < 4; ri++) { acc[ri][0] = 0ull; acc[ri][1] = 0ull; }

    const ulonglong2* Wu = (const ulonglong2*)Wsm;

    for (int d0 = 0; d0 < D_IN; d0 += 4) {
        float4 xv[4];
#pragma unroll
        for (int ri = 0; ri < 4; ri++)
            xv[ri] = *(const float4*)&xsm[(r0 + ri) * D_IN + d0];
#pragma unroll
        for (int dd = 0; dd < 4; dd++) {
            ulonglong2 wv = Wu[(d0 + dd) * 8 + k4];
#pragma unroll
            for (int ri = 0; ri < 4; ri++) {
                ull x2 = pack2(((const float*)&xv[ri])[dd]);
                ffma2(acc[ri][0], wv.x, x2);
                ffma2(acc[ri][1], wv.y, x2);
            }
        }
    }

    float* out = g_h + ((size_t)hb * N_NODES + seg * 128) * D_H;
#pragma unroll
    for (int ri = 0; ri < 4; ri++) {
        float4 v;
        v.x = lo32(acc[ri][0]); v.y = hi32(acc[ri][0]);
        v.z = lo32(acc[ri][1]); v.w = hi32(acc[ri][1]);
        *(float4*)&out[(r0 + ri) * D_H + k4 * 4] = v;
    }
}

// ---------------------------------------------------------------------------
// Kernel 2: attention via branch factorization + counting buckets (NO sort).
//   p_ij = exp(lrelu(et_i+es_j)) = u_i*v_j (s>0) | u2_i*v2_j (s<0)
// Bucket j by es_j (64 equal-width buckets); per-bucket partial sums of
// v*h / v2*h; exclusive prefix over buckets; per-row: ALU bucket index +
// exact predicated partial over the boundary bucket. Deterministic
// (ballot/rank scatter, no atomics). ~95.5 KB smem -> 2 CTA/SM, 1 wave.
// Output overwrites g_h slice in place.
// ---------------------------------------------------------------------------
__global__ void __launch_bounds__(256, 2) att_kernel(const float* __restrict__ att_src,
                                                     const float* __restrict__ att_tar) {
    extern __shared__ float smem[];
    float* hsm  = smem;                        // 512*32
    float* esrc = hsm + N_NODES * D_H;         // 512
    float* etar = esrc + 512;                  // 512
    float* vsp  = etar + 512;                  // 512 (permuted)
    float* v2sp = vsp + 512;                   // 512 (permuted)
    int*   bkta = (int*)(v2sp + 512);          // 512
    int*   perm = bkta + 512;                  // 512
    int*   counts = perm + 512;                // 64
    int*   base = counts + NB;                 // 65
    float* Lc1  = (float*)(base + NB + 1);     // 65*32
    float* Lc2  = Lc1 + (NB + 1) * 32;         // 65*32
    float* cv1  = Lc2 + (NB + 1) * 32;         // 65
    float* cv2  = cv1 + NB + 1;                // 65
    float* stats = cv2 + NB + 1;               // 2: emin, inv

    const int hb = blockIdx.x;
    const int h = hb >> 5;
    const int tid = threadIdx.x;
    const int wid = tid >> 5;
    const int lane = tid & 31;
    const unsigned FULL = 0xffffffffu;

    float* gslice = g_h + (size_t)hb * N_NODES * D_H;

    // ---- load h tile (64 KB) ----
    {
        const float4* src = (const float4*)gslice;
        float4* dst = (float4*)hsm;
        for (int i = tid; i < N_NODES * D_H / 4; i += 256) dst[i] = src[i];
    }
    __syncthreads();

    // ---- e_src / e_tar dot products (warp per row) ----
    {
        const float as = att_src[h * D_H + lane];
        const float at = att_tar[h * D_H + lane];
        for (int j = wid; j < N_NODES; j += 8) {
            float v = hsm[j * D_H + lane];
            float s1 = v * as;
            float s2 = v * at;
#pragma unroll
            for (int off = 16; off; off >>= 1) {
                s1 += __shfl_xor_sync(FULL, s1, off);
                s2 += __shfl_xor_sync(FULL, s2, off);
            }
            if (lane == 0) { esrc[j] = s1; etar[j] = s2; }
        }
    }
    __syncthreads();

    // ---- min/max of esrc (warp 0) -> bucket scale ----
    if (wid == 0) {
        float mn = 1e30f, mx = -1e30f;
        for (int j = lane; j < N_NODES; j += 32) {
            float e = esrc[j];
            mn = fminf(mn, e); mx = fmaxf(mx, e);
        }
#pragma unroll
        for (int off = 16; off; off >>= 1) {
            mn = fminf(mn, __shfl_xor_sync(FULL, mn, off));
            mx = fmaxf(mx, __shfl_xor_sync(FULL, mx, off));
        }
        if (lane == 0) {
            stats[0] = mn;
            stats[1] = (float)NB / fmaxf(mx - mn, 1e-30f);
        }
    }
    __syncthreads();

    const float emin = stats[0];
    const float binv = stats[1];

    // ---- bucket index per j ----
    for (int j = tid; j < N_NODES; j += 256) {
        int c = (int)((esrc[j] - emin) * binv);
        bkta[j] = min(c, NB - 1);
    }
    __syncthreads();

    // ---- histogram (ballot) : warp w owns buckets [8w, 8w+8) ----
    int myb[16];
#pragma unroll
    for (int q = 0; q < 16; q++) myb[q] = bkta[q * 32 + lane];
    {
        const int c0 = wid * 8;
#pragma unroll
        for (int cc = 0; cc < 8; cc++) {
            int cnt = 0;
#pragma unroll
            for (int q = 0; q < 16; q++)
                cnt += __popc(__ballot_sync(FULL, myb[q] == c0 + cc));
            if (lane == 0) counts[c0 + cc] = cnt;
        }
    }
    __syncthreads();

    // ---- exclusive scan of counts (warp 0, 64 elems as 2x32) ----
    if (wid == 0) {
        int a0 = counts[lane], a1 = counts[32 + lane];
        int s0 = a0, s1 = a1;
#pragma unroll
        for (int off = 1; off < 32; off <<= 1) {
            int t0 = __shfl_up_sync(FULL, s0, off);
            int t1 = __shfl_up_sync(FULL, s1, off);
            if (lane >= off) { s0 += t0; s1 += t1; }
        }
        int tot0 = __shfl_sync(FULL, s0, 31);
        base[lane] = s0 - a0;
        base[32 + lane] = tot0 + s1 - a1;
        if (lane == 31) base[64] = tot0 + s1;
    }
    __syncthreads();

    // ---- rank scatter (deterministic): perm, vsp, v2sp ----
    {
        const int c0 = wid * 8;
        const unsigned ltmask = (1u << lane) - 1u;
#pragma unroll
        for (int cc = 0; cc < 8; cc++) {
            int off = base[c0 + cc];
#pragma unroll
            for (int q = 0; q < 16; q++) {
                unsigned bal = __ballot_sync(FULL, myb[q] == c0 + cc);
                if (myb[q] == c0 + cc) {
                    int pos = off + __popc(bal & ltmask);
                    int j = q * 32 + lane;
                    float e = esrc[j];
                    perm[pos] = j;
                    vsp[pos]  = ex2f(e * L2E);
                    v2sp[pos] = ex2f(e * C02);
                }
                off += __popc(bal);
            }
        }
    }
    __syncthreads();

    // ---- per-bucket partial sums of v*h, v2*h (warp w: buckets [8w,8w+8)) ----
    {
        const int c0 = wid * 8;
#pragma unroll
        for (int cc = 0; cc < 8; cc++) {
            const int c = c0 + cc;
            float l1 = 0.f, l2 = 0.f;
            const int e0 = base[c], e1 = base[c + 1];
            for (int t = e0; t < e1; t++) {
                int j = perm[t];
                float x = hsm[j * D_H + lane];
                l1 = fmaf(vsp[t], x, l1);
                l2 = fmaf(v2sp[t], x, l2);
            }
            Lc1[c * 32 + lane] = l1;
            Lc2[c * 32 + lane] = l2;
        }
    }
    // scalar bucket sums (one thread per bucket)
    if (tid < NB) {
        float s1 = 0.f, s2 = 0.f;
        for (int t = base[tid]; t < base[tid + 1]; t++) {
            s1 += vsp[t]; s2 += v2sp[t];
        }
        cv1[tid] = s1; cv2[tid] = s2;
    }
    __syncthreads();

    // ---- exclusive scans over buckets ----
    if (wid == 0) {
        float run = 0.f;
#pragma unroll
        for (int c = 0; c < NB; c++) {
            float t = Lc1[c * 32 + lane]; Lc1[c * 32 + lane] = run; run += t;
        }
        Lc1[NB * 32 + lane] = run;
    } else if (wid == 1) {
        float run = 0.f;
#pragma unroll
        for (int c = 0; c < NB; c++) {
            float t = Lc2[c * 32 + lane]; Lc2[c * 32 + lane] = run; run += t;
        }
        Lc2[NB * 32 + lane] = run;
    } else if (wid == 2 || wid == 3) {
        float* cv = (wid == 2) ? cv1 : cv2;
        float a0 = cv[lane], a1 = cv[32 + lane];
        float s0 = a0, s1 = a1;
#pragma unroll
        for (int off = 1; off < 32; off <<= 1) {
            float t0 = __shfl_up_sync(FULL, s0, off);
            float t1 = __shfl_up_sync(FULL, s1, off);
            if (lane >= off) { s0 += t0; s1 += t1; }
        }
        float tot0 = __shfl_sync(FULL, s0, 31);
        cv[lane] = s0 - a0;
        cv[32 + lane] = tot0 + s1 - a1;
        if (lane == 31) cv[64] = tot0 + s1;
    }
    __syncthreads();

    // ---- per-row combine: warp w -> rows [64w, 64w+64) ----
    {
        const float Tv1 = cv1[NB];
        const float T1k = Lc1[NB * 32 + lane];
        for (int r = 0; r < 64; r++) {
            const int i = wid * 64 + r;
            const float et = etar[i];
            const float thr = -et;
            int c = (int)((thr - emin) * binv);
            c = min(NB - 1, max(0, c));

            float S1 = Lc1[c * 32 + lane];
            float S2 = Lc2[c * 32 + lane];
            float Sv1 = cv1[c];
            float Sv2 = cv2[c];
            const int e1 = base[c + 1];
            for (int t = base[c]; t < e1; t++) {
                int j = perm[t];
                if (esrc[j] < thr) {
                    float x = hsm[j * D_H + lane];
                    float a = vsp[t], b2 = v2sp[t];
                    S1 = fmaf(a, x, S1);
                    S2 = fmaf(b2, x, S2);
                    Sv1 += a; Sv2 += b2;
                }
            }
            float es = esrc[i];
            float u  = ex2f(et * L2E);
            float u2 = ex2f(et * C02);
            float s = et + es;
            float ps = ex2f(fmaf(fmaxf(s, 0.f), L2E, fminf(s, 0.f) * C02));
            float denom = u * (Tv1 - Sv1) + u2 * Sv2 - ps;
            float sc = 1.f / denom;
            float hx = hsm[i * D_H + lane];
            gslice[i * D_H + lane] = (u * (T1k - S1) + u2 * S2 - ps * hx) * sc;
        }
    }
}

// ---------------------------------------------------------------------------
// Kernel 3: msgs = tanh(mean_h(head_msgs) + bias); GRU gated update -> out
// grid = B * 8 (64-row chunks), 256 threads. d-outer loop: W loaded once per
// d and reused across 8 rows (4x fewer LDS than e-outer).
// ---------------------------------------------------------------------------
__global__ void __launch_bounds__(256) gru_kernel(const float* __restrict__ inputs,
                           const float* __restrict__ hidden,
                           const float* __restrict__ bias,
                           const float* __restrict__ W_hr,
                           const float* __restrict__ W_hi,
                           const float* __restrict__ W_hm,
                           const float* __restrict__ W_ir,
                           const float* __restrict__ b_ir,
                           const float* __restrict__ W_ii,
                           const float* __restrict__ b_ii,
                           const float* __restrict__ W_in,
                           const float* __restrict__ b_in,
                           float* __restrict__ out) {
    extern __shared__ float smem[];
    float* Wir = smem;                    // 2048
    float* Wii = Wir + D_IN * D_H;        // 2048
    float* Win = Wii + D_IN * D_H;        // 2048
    float* Whr = Win + D_IN * D_H;        // 1024
    float* Whi = Whr + D_H * D_H;         // 1024
    float* Whm = Whi + D_H * D_H;         // 1024
    float* xsm = Whm + D_H * D_H;         // 64*64
    float* msm = xsm + 64 * D_IN;         // 64*32

    const int b = blockIdx.x >> 3;
    const int n0 = (blockIdx.x & 7) * 64;

    for (int i = threadIdx.x; i < D_IN * D_H; i += 256) {
        Wir[i] = W_ir[i]; Wii[i] = W_ii[i]; Win[i] = W_in[i];
    }
    for (int i = threadIdx.x; i < D_H * D_H; i += 256) {
        Whr[i] = W_hr[i]; Whi[i] = W_hi[i]; Whm[i] = W_hm[i];
    }
    for (int i = threadIdx.x; i < 64 * D_IN / 4; i += 256)
        ((float4*)xsm)[i] =
            ((const float4*)(inputs + ((size_t)b * N_NODES + n0) * D_IN))[i];

    // mean over heads + bias + tanh
    for (int i = threadIdx.x; i < 64 * D_H / 4; i += 256) {
        float4 acc = make_float4(0.f, 0.f, 0.f, 0.f);
#pragma unroll
        for (int h = 0; h < H_HEADS; h++) {
            const float4* src = (const float4*)(g_h +
                ((size_t)(h * B_SZ + b) * N_NODES + n0) * D_H);
            float4 v = src[i];
            acc.x += v.x; acc.y += v.y; acc.z += v.z; acc.w += v.w;
        }
        int k4 = (i & 7) * 4;
        float4 r;
        r.x = tanhf(acc.x * 0.125f + bias[k4 + 0]);
        r.y = tanhf(acc.y * 0.125f + bias[k4 + 1]);
        r.z = tanhf(acc.z * 0.125f + bias[k4 + 2]);
        r.w = tanhf(acc.w * 0.125f + bias[k4 + 3]);
        ((float4*)msm)[i] = r;
    }
    __syncthreads();

    const int k = threadIdx.x & 31;
    const int r0 = threadIdx.x >> 5;   // warp id -> broadcast-friendly rows

    float xr[8], xi[8], xn[8];
    {
        const float br = b_ir[k], bi = b_ii[k], bn = b_in[k];
#pragma unroll
        for (int e = 0; e < 8; e++) { xr[e] = br; xi[e] = bi; xn[e] = bn; }
    }
    for (int d = 0; d < D_IN; d++) {
        const float wr = Wir[d * D_H + k];
        const float wi = Wii[d * D_H + k];
        const float wn = Win[d * D_H + k];
#pragma unroll
        for (int e = 0; e < 8; e++) {
            float x = xsm[(r0 + 8 * e) * D_IN + d];
            xr[e] = fmaf(x, wr, xr[e]);
            xi[e] = fmaf(x, wi, xi[e]);
            xn[e] = fmaf(x, wn, xn[e]);
        }
    }
    float hr[8], hi[8], hm[8];
#pragma unroll
    for (int e = 0; e < 8; e++) { hr[e] = 0.f; hi[e] = 0.f; hm[e] = 0.f; }
    for (int d = 0; d < D_H; d++) {
        const float wr = Whr[d * D_H + k];
        const float wi = Whi[d * D_H + k];
        const float wm = Whm[d * D_H + k];
#pragma unroll
        for (int e = 0; e < 8; e++) {
            float mm = msm[(r0 + 8 * e) * D_H + d];
            hr[e] = fmaf(mm, wr, hr[e]);
            hi[e] = fmaf(mm, wi, hi[e]);
            hm[e] = fmaf(mm, wm, hm[e]);
        }
    }
#pragma unroll
    for (int e = 0; e < 8; e++) {
        const int r = r0 + 8 * e;
        float mg = 1.f / (1.f + __expf(-(xr[e] + hr[e])));
        float ig = 1.f / (1.f + __expf(-(xi[e] + hi[e])));
        float nn = tanhf(xn[e] + mg * hm[e]);
        const size_t idx = ((size_t)b * N_NODES + n0 + r) * D_H + k;
        out[idx] = ig * nn + (1.f - ig) * hidden[idx];
    }
}

// ---------------------------------------------------------------------------
// Launch
// ---------------------------------------------------------------------------
extern "C" void kernel_launch(void* const* d_in, const int* in_sizes, int n_in,
                              void* d_out, int out_size) {
    const float* inputs  = (const float*)d_in[0];
    const float* hidden  = (const float*)d_in[1];
    const float* linear  = (const float*)d_in[2];
    const float* bias    = (const float*)d_in[3];
    const float* att_src = (const float*)d_in[4];
    const float* att_tar = (const float*)d_in[5];
    const float* W_hr    = (const float*)d_in[6];
    const float* W_hi    = (const float*)d_in[7];
    const float* W_hm    = (const float*)d_in[8];
    const float* W_ir    = (const float*)d_in[9];
    const float* b_ir    = (const float*)d_in[10];
    const float* W_ii    = (const float*)d_in[11];
    const float* b_ii    = (const float*)d_in[12];
    const float* W_in    = (const float*)d_in[13];
    const float* b_in    = (const float*)d_in[14];
    float* out = (float*)d_out;

    // floats: hsm 16384 + es/et/vsp/v2sp 2048 + ints 1153 + Lc 4160 + cv 130 + 2
    const int att_smem = (16384 + 4 * 512 + 512 + 512 + NB + NB + 1 +
                          2 * (NB + 1) * 32 + 2 * (NB + 1) + 2) * sizeof(float);
    const int gru_smem = (3 * D_IN * D_H + 3 * D_H * D_H + 64 * D_IN + 64 * D_H)
                         * sizeof(float);                          // 61440

    static bool attr_done = false;
    if (!attr_done) {
        cudaFuncSetAttribute(att_kernel, cudaFuncAttributeMaxDynamicSharedMemorySize,
                             att_smem);
        cudaFuncSetAttribute(gru_kernel, cudaFuncAttributeMaxDynamicSharedMemorySize,
                             gru_smem);
        attr_done = true;
    }

    proj_kernel<<<H_HEADS * B_SZ * 4, 256>>>(inputs, linear);
    att_kernel<<<H_HEADS * B_SZ, 256, att_smem>>>(att_src, att_tar);
    gru_kernel<<<B_SZ * 8, 256, gru_smem>>>(inputs, hidden, bias,
                                            W_hr, W_hi, W_hm,
                                            W_ir, b_ir, W_ii, b_ii, W_in, b_in,
                                            out);
}

// round 12
// speedup vs baseline: 1.3812x; 1.3812x over previous
#include <cuda_runtime.h>
#include <cstdint>

#define H_HEADS 8
#define D_IN 64
#define D_H 32
#define B_SZ 32
#define N_NODES 512
#define NC 32                      /* sorted-rank chunks */
#define CSZ 16                     /* chunk size */

typedef unsigned long long ull;

// Scratch: h[h][b][n][k]; attention overwrites each slice in place with the
// per-head aggregated messages; gru averages heads.
__device__ float g_h[H_HEADS * B_SZ * N_NODES * D_H];    // 16 MB

__device__ __forceinline__ ull pack2(float x) {
    ull r; asm("mov.b64 %0, {%1, %1};" : "=l"(r) : "f"(x)); return r;
}
__device__ __forceinline__ void ffma2(ull& acc, ull a, ull b) {
    asm("fma.rn.f32x2 %0, %1, %2, %0;" : "+l"(acc) : "l"(a), "l"(b));
}
__device__ __forceinline__ float lo32(ull v) {
    return __uint_as_float((unsigned)(v & 0xffffffffull));
}
__device__ __forceinline__ float hi32(ull v) {
    return __uint_as_float((unsigned)(v >> 32));
}
__device__ __forceinline__ float ex2f(float t) {
    float p; asm("ex2.approx.f32 %0, %1;" : "=f"(p) : "f"(t)); return p;
}
__device__ __forceinline__ unsigned flipf(float x) {
    unsigned u = __float_as_uint(x);
    unsigned mask = (unsigned)((int)u >> 31) | 0x80000000u;
    return u ^ mask;
}
__device__ __forceinline__ float unflipf(unsigned u) {
    unsigned mask = (u & 0x80000000u) ? 0x80000000u : 0xffffffffu;
    return __uint_as_float(u ^ mask);
}

#define L2E 1.4426950408889634f
#define C02 0.28853900817779268f   /* 0.2 * log2(e) */

// ---------------------------------------------------------------------------
// Kernel 1: h[h,b,n,k] = sum_d inputs[b,n,d] * linear[h,d,k]
// grid = H*B*4 (128-row segments), 256 threads. Thread = 4 rows x 4 cols.
// (Best measured proj config: 23.4 us.)
// ---------------------------------------------------------------------------
__global__ void __launch_bounds__(256) proj_kernel(const float* __restrict__ inputs,
                                                   const float* __restrict__ linear) {
    const int blk = blockIdx.x;
    const int hb = blk >> 2;
    const int seg = blk & 3;
    const int h = hb >> 5;
    const int b = hb & 31;

    __shared__ __align__(16) float Wsm[D_IN * D_H];   // 8 KB
    __shared__ __align__(16) float xsm[128 * D_IN];   // 32 KB

    {
        const float4* W4 = (const float4*)(linear + h * D_IN * D_H);
        float4* Ws4 = (float4*)Wsm;
        for (int i = threadIdx.x; i < D_IN * D_H / 4; i += 256) Ws4[i] = W4[i];
        const float4* x4 = (const float4*)(inputs +
                           ((size_t)b * N_NODES + seg * 128) * D_IN);
        float4* xs4 = (float4*)xsm;
        for (int i = threadIdx.x; i < 128 * D_IN / 4; i += 256) xs4[i] = x4[i];
    }
    __syncthreads();

    const int k4 = threadIdx.x & 7;        // 16B column chunk (4 cols)
    const int r0 = (threadIdx.x >> 3) * 4; // local row base (0..124)

    ull acc[4][2];
#pragma unroll
    for (int ri = 0; ri < 4; ri++) { acc[ri][0] = 0ull; acc[ri][1] = 0ull; }

    const ulonglong2* Wu = (const ulonglong2*)Wsm;

    for (int d0 = 0; d0 < D_IN; d0 += 4) {
        float4 xv[4];
#pragma unroll
        for (int ri = 0; ri < 4; ri++)
            xv[ri] = *(const float4*)&xsm[(r0 + ri) * D_IN + d0];
#pragma unroll
        for (int dd = 0; dd < 4; dd++) {
            ulonglong2 wv = Wu[(d0 + dd) * 8 + k4];
#pragma unroll
            for (int ri = 0; ri < 4; ri++) {
                ull x2 = pack2(((const float*)&xv[ri])[dd]);
                ffma2(acc[ri][0], wv.x, x2);
                ffma2(acc[ri][1], wv.y, x2);
            }
        }
    }

    float* out = g_h + ((size_t)hb * N_NODES + seg * 128) * D_H;
#pragma unroll
    for (int ri = 0; ri < 4; ri++) {
        float4 v;
        v.x = lo32(acc[ri][0]); v.y = hi32(acc[ri][0]);
        v.z = lo32(acc[ri][1]); v.w = hi32(acc[ri][1]);
        *(float4*)&out[(r0 + ri) * D_H + k4 * 4] = v;
    }
}

// ---------------------------------------------------------------------------
// Kernel 2: attention via branch factorization + sort + balanced rank chunks.
//   p_ij = exp(lrelu(et_i+es_j)) = u_i*v_j (s>0) | u2_i*v2_j (s<0)
// Sort j by es_j (bitonic). 32 chunks of 16 sorted ranks -> per-chunk partial
// sums (balanced across warps), exclusive scans, per-thread binary search for
// each row's threshold rank, per-row <=15-element remainder. No serial sweep,
// no data-dependent imbalance. ~88.6 KB smem -> 2 CTA/SM, 1 wave.
// Output overwrites g_h slice in place.
// ---------------------------------------------------------------------------
__global__ void __launch_bounds__(256, 2) att_kernel(const float* __restrict__ att_src,
                                                     const float* __restrict__ att_tar) {
    extern __shared__ float smem[];
    float* hsm  = smem;                        // 512*32 = 16384
    float* uni  = hsm + N_NODES * D_H;
    ull*   keys = (ull*)uni;                   // 512 ull (1024 f)
    float* esrc = uni + 1024;                  // 512
    float* etar = uni + 1536;                  // 512
    float* vs   = uni + 2048;                  // 512 (sorted order)
    float* v2s  = uni + 2560;                  // 512
    int*   tarr = (int*)(uni + 3072);          // 512
    float* Lc1  = uni + 3584;                  // 33*32
    float* Lc2  = Lc1 + (NC + 1) * 32;         // 33*32
    float* cv1  = Lc2 + (NC + 1) * 32;         // 33
    float* cv2  = cv1 + NC + 1;                // 33

    const int hb = blockIdx.x;
    const int h = hb >> 5;
    const int tid = threadIdx.x;
    const int wid = tid >> 5;
    const int lane = tid & 31;
    const unsigned FULL = 0xffffffffu;

    float* gslice = g_h + (size_t)hb * N_NODES * D_H;

    // ---- load h tile (64 KB) ----
    {
        const float4* src = (const float4*)gslice;
        float4* dst = (float4*)hsm;
        for (int i = tid; i < N_NODES * D_H / 4; i += 256) dst[i] = src[i];
    }
    __syncthreads();

    // ---- e_src / e_tar dot products (warp per row) ----
    {
        const float as = att_src[h * D_H + lane];
        const float at = att_tar[h * D_H + lane];
        for (int j = wid; j < N_NODES; j += 8) {
            float v = hsm[j * D_H + lane];
            float s1 = v * as;
            float s2 = v * at;
#pragma unroll
            for (int off = 16; off; off >>= 1) {
                s1 += __shfl_xor_sync(FULL, s1, off);
                s2 += __shfl_xor_sync(FULL, s2, off);
            }
            if (lane == 0) { esrc[j] = s1; etar[j] = s2; }
        }
    }
    __syncthreads();

    // ---- sort keys by es (asc): key = flip(es) << 32 | j ----
    for (int i = tid; i < N_NODES; i += 256)
        keys[i] = ((ull)flipf(esrc[i]) << 32) | (unsigned)i;
    for (int k2 = 2; k2 <= N_NODES; k2 <<= 1) {
        for (int j2 = k2 >> 1; j2 > 0; j2 >>= 1) {
            __syncthreads();
            for (int i = tid; i < N_NODES; i += 256) {
                int ixj = i ^ j2;
                if (ixj > i) {
                    ull a = keys[i], bb = keys[ixj];
                    if ((a > bb) == ((i & k2) == 0)) { keys[i] = bb; keys[ixj] = a; }
                }
            }
        }
    }
    __syncthreads();

    // ---- vs/v2s at sorted rank + per-thread binary searches (2 rows) ----
    for (int t = tid; t < N_NODES; t += 256) {
        float e = unflipf((unsigned)(keys[t] >> 32));
        vs[t]  = ex2f(e * L2E);
        v2s[t] = ex2f(e * C02);
    }
#pragma unroll
    for (int rr = 0; rr < 2; rr++) {
        int i = tid + rr * 256;
        ull target = ((ull)flipf(-etar[i])) << 32;
        int lo = 0, hi = N_NODES;
#pragma unroll
        for (int it = 0; it < 9; it++) {
            int mid = (lo + hi) >> 1;
            if (keys[mid] < target) lo = mid + 1; else hi = mid;
        }
        tarr[i] = lo;
    }
    __syncthreads();

    // ---- chunk partial sums (32 chunks of 16, 4 chunks/warp: balanced) ----
    for (int c = wid; c < NC; c += 8) {
        float l1 = 0.f, l2 = 0.f;
#pragma unroll 4
        for (int tt = 0; tt < CSZ; tt++) {
            int t = c * CSZ + tt;
            int j = (int)(unsigned)(keys[t] & 0xffffffffull);
            float x = hsm[j * D_H + lane];
            l1 = fmaf(vs[t], x, l1);
            l2 = fmaf(v2s[t], x, l2);
        }
        Lc1[c * 32 + lane] = l1;
        Lc2[c * 32 + lane] = l2;
        // scalar chunk sums: half-warp reductions (lanes 0-15: v, 16-31: v2)
        float sv = (lane < 16) ? vs[c * CSZ + lane] : v2s[c * CSZ + (lane - 16)];
#pragma unroll
        for (int off = 8; off; off >>= 1)
            sv += __shfl_xor_sync(FULL, sv, off);
        if (lane == 0) cv1[c] = sv;
        if (lane == 16) cv2[c] = sv;
    }
    __syncthreads();

    // ---- exclusive scans over chunks ----
    if (wid == 0) {
        float run = 0.f;
#pragma unroll
        for (int c = 0; c < NC; c++) {
            float t = Lc1[c * 32 + lane]; Lc1[c * 32 + lane] = run; run += t;
        }
        Lc1[NC * 32 + lane] = run;
    } else if (wid == 1) {
        float run = 0.f;
#pragma unroll
        for (int c = 0; c < NC; c++) {
            float t = Lc2[c * 32 + lane]; Lc2[c * 32 + lane] = run; run += t;
        }
        Lc2[NC * 32 + lane] = run;
    } else if (wid == 2) {
        float x = cv1[lane];
        float inc = x;
#pragma unroll
        for (int off = 1; off < 32; off <<= 1) {
            float y = __shfl_up_sync(FULL, inc, off);
            if (lane >= off) inc += y;
        }
        cv1[lane] = inc - x;
        if (lane == 31) cv1[NC] = inc;
    } else if (wid == 3) {
        float x = cv2[lane];
        float inc = x;
#pragma unroll
        for (int off = 1; off < 32; off <<= 1) {
            float y = __shfl_up_sync(FULL, inc, off);
            if (lane >= off) inc += y;
        }
        cv2[lane] = inc - x;
        if (lane == 31) cv2[NC] = inc;
    }
    __syncthreads();

    // ---- per-row combine: warp w -> rows [64w, 64w+64) ----
    {
        const float Tv1 = cv1[NC];
        const float T1k = Lc1[NC * 32 + lane];
        for (int r = 0; r < 64; r++) {
            const int i = wid * 64 + r;
            const int t = tarr[i];
            const int c = t >> 4;          // CSZ = 16
            float S1 = Lc1[c * 32 + lane];
            float S2 = Lc2[c * 32 + lane];
            float Sv1 = cv1[c];
            float Sv2 = cv2[c];
            const int t0 = c << 4;
#pragma unroll 4
            for (int tp = t0; tp < t; tp++) {
                int j = (int)(unsigned)(keys[tp] & 0xffffffffull);
                float x = hsm[j * D_H + lane];
                float a = vs[tp], b2 = v2s[tp];
                S1 = fmaf(a, x, S1);
                S2 = fmaf(b2, x, S2);
                Sv1 += a; Sv2 += b2;
            }
            float et = etar[i];
            float es = esrc[i];
            float u  = ex2f(et * L2E);
            float u2 = ex2f(et * C02);
            float s = et + es;
            float ps = ex2f(fmaf(fmaxf(s, 0.f), L2E, fminf(s, 0.f) * C02));
            float denom = u * (Tv1 - Sv1) + u2 * Sv2 - ps;
            float sc = 1.f / denom;
            float hx = hsm[i * D_H + lane];
            gslice[i * D_H + lane] = (u * (T1k - S1) + u2 * S2 - ps * hx) * sc;
        }
    }
}

// ---------------------------------------------------------------------------
// Kernel 3: msgs = tanh(mean_h(head_msgs) + bias); GRU gated update -> out
// grid = B * 8 (64-row chunks), 256 threads. d-outer: W loaded once per d,
// reused across 8 rows (4x fewer LDS than e-outer).
// ---------------------------------------------------------------------------
__global__ void __launch_bounds__(256) gru_kernel(const float* __restrict__ inputs,
                           const float* __restrict__ hidden,
                           const float* __restrict__ bias,
                           const float* __restrict__ W_hr,
                           const float* __restrict__ W_hi,
                           const float* __restrict__ W_hm,
                           const float* __restrict__ W_ir,
                           const float* __restrict__ b_ir,
                           const float* __restrict__ W_ii,
                           const float* __restrict__ b_ii,
                           const float* __restrict__ W_in,
                           const float* __restrict__ b_in,
                           float* __restrict__ out) {
    extern __shared__ float smem[];
    float* Wir = smem;                    // 2048
    float* Wii = Wir + D_IN * D_H;        // 2048
    float* Win = Wii + D_IN * D_H;        // 2048
    float* Whr = Win + D_IN * D_H;        // 1024
    float* Whi = Whr + D_H * D_H;         // 1024
    float* Whm = Whi + D_H * D_H;         // 1024
    float* xsm = Whm + D_H * D_H;         // 64*64
    float* msm = xsm + 64 * D_IN;         // 64*32

    const int b = blockIdx.x >> 3;
    const int n0 = (blockIdx.x & 7) * 64;

    for (int i = threadIdx.x; i < D_IN * D_H; i += 256) {
        Wir[i] = W_ir[i]; Wii[i] = W_ii[i]; Win[i] = W_in[i];
    }
    for (int i = threadIdx.x; i < D_H * D_H; i += 256) {
        Whr[i] = W_hr[i]; Whi[i] = W_hi[i]; Whm[i] = W_hm[i];
    }
    for (int i = threadIdx.x; i < 64 * D_IN / 4; i += 256)
        ((float4*)xsm)[i] =
            ((const float4*)(inputs + ((size_t)b * N_NODES + n0) * D_IN))[i];

    // mean over heads + bias + tanh
    for (int i = threadIdx.x; i < 64 * D_H / 4; i += 256) {
        float4 acc = make_float4(0.f, 0.f, 0.f, 0.f);
#pragma unroll
        for (int h = 0; h < H_HEADS; h++) {
            const float4* src = (const float4*)(g_h +
                ((size_t)(h * B_SZ + b) * N_NODES + n0) * D_H);
            float4 v = src[i];
            acc.x += v.x; acc.y += v.y; acc.z += v.z; acc.w += v.w;
        }
        int k4 = (i & 7) * 4;
        float4 r;
        r.x = tanhf(acc.x * 0.125f + bias[k4 + 0]);
        r.y = tanhf(acc.y * 0.125f + bias[k4 + 1]);
        r.z = tanhf(acc.z * 0.125f + bias[k4 + 2]);
        r.w = tanhf(acc.w * 0.125f + bias[k4 + 3]);
        ((float4*)msm)[i] = r;
    }
    __syncthreads();

    const int k = threadIdx.x & 31;
    const int r0 = threadIdx.x >> 5;

    float xr[8], xi[8], xn[8];
    {
        const float br = b_ir[k], bi = b_ii[k], bn = b_in[k];
#pragma unroll
        for (int e = 0; e < 8; e++) { xr[e] = br; xi[e] = bi; xn[e] = bn; }
    }
    for (int d = 0; d < D_IN; d++) {
        const float wr = Wir[d * D_H + k];
        const float wi = Wii[d * D_H + k];
        const float wn = Win[d * D_H + k];
#pragma unroll
        for (int e = 0; e < 8; e++) {
            float x = xsm[(r0 + 8 * e) * D_IN + d];
            xr[e] = fmaf(x, wr, xr[e]);
            xi[e] = fmaf(x, wi, xi[e]);
            xn[e] = fmaf(x, wn, xn[e]);
        }
    }
    float hr[8], hi[8], hm[8];
#pragma unroll
    for (int e = 0; e < 8; e++) { hr[e] = 0.f; hi[e] = 0.f; hm[e] = 0.f; }
    for (int d = 0; d < D_H; d++) {
        const float wr = Whr[d * D_H + k];
        const float wi = Whi[d * D_H + k];
        const float wm = Whm[d * D_H + k];
#pragma unroll
        for (int e = 0; e < 8; e++) {
            float mm = msm[(r0 + 8 * e) * D_H + d];
            hr[e] = fmaf(mm, wr, hr[e]);
            hi[e] = fmaf(mm, wi, hi[e]);
            hm[e] = fmaf(mm, wm, hm[e]);
        }
    }
#pragma unroll
    for (int e = 0; e < 8; e++) {
        const int r = r0 + 8 * e;
        float mg = 1.f / (1.f + __expf(-(xr[e] + hr[e])));
        float ig = 1.f / (1.f + __expf(-(xi[e] + hi[e])));
        float nn = tanhf(xn[e] + mg * hm[e]);
        const size_t idx = ((size_t)b * N_NODES + n0 + r) * D_H + k;
        out[idx] = ig * nn + (1.f - ig) * hidden[idx];
    }
}

// ---------------------------------------------------------------------------
// Launch
// ---------------------------------------------------------------------------
extern "C" void kernel_launch(void* const* d_in, const int* in_sizes, int n_in,
                              void* d_out, int out_size) {
    const float* inputs  = (const float*)d_in[0];
    const float* hidden  = (const float*)d_in[1];
    const float* linear  = (const float*)d_in[2];
    const float* bias    = (const float*)d_in[3];
    const float* att_src = (const float*)d_in[4];
    const float* att_tar = (const float*)d_in[5];
    const float* W_hr    = (const float*)d_in[6];
    const float* W_hi    = (const float*)d_in[7];
    const float* W_hm    = (const float*)d_in[8];
    const float* W_ir    = (const float*)d_in[9];
    const float* b_ir    = (const float*)d_in[10];
    const float* W_ii    = (const float*)d_in[11];
    const float* b_ii    = (const float*)d_in[12];
    const float* W_in    = (const float*)d_in[13];
    const float* b_in    = (const float*)d_in[14];
    float* out = (float*)d_out;

    const int att_smem = (16384 + 1024 + 4 * 512 + 512 +
                          2 * (NC + 1) * 32 + 2 * (NC + 1)) * sizeof(float);
    const int gru_smem = (3 * D_IN * D_H + 3 * D_H * D_H + 64 * D_IN + 64 * D_H)
                         * sizeof(float);                          // 61440

    static bool attr_done = false;
    if (!attr_done) {
        cudaFuncSetAttribute(att_kernel, cudaFuncAttributeMaxDynamicSharedMemorySize,
                             att_smem);
        cudaFuncSetAttribute(gru_kernel, cudaFuncAttributeMaxDynamicSharedMemorySize,
                             gru_smem);
        attr_done = true;
    }

    proj_kernel<<<H_HEADS * B_SZ * 4, 256>>>(inputs, linear);
    att_kernel<<<H_HEADS * B_SZ, 256, att_smem>>>(att_src, att_tar);
    gru_kernel<<<B_SZ * 8, 256, gru_smem>>>(inputs, hidden, bias,
                                            W_hr, W_hi, W_hm,
                                            W_ir, b_ir, W_ii, b_ii, W_in, b_in,
                                            out);
}

// round 13
// speedup vs baseline: 1.5802x; 1.1440x over previous
#include <cuda_runtime.h>
#include <cstdint>

#define H_HEADS 8
#define D_IN 64
#define D_H 32
#define B_SZ 32
#define N_NODES 512
#define NC 32                      /* sorted-rank chunks */
#define CSZ 16                     /* chunk size */
#define XST 68                     /* padded xsm row stride (floats) */

typedef unsigned long long ull;

// Scratch: h[h][b][n][k]; attention overwrites each slice in place with the
// per-head aggregated messages; gru averages heads.
__device__ float g_h[H_HEADS * B_SZ * N_NODES * D_H];    // 16 MB

__device__ __forceinline__ ull pack2(float x) {
    ull r; asm("mov.b64 %0, {%1, %1};" : "=l"(r) : "f"(x)); return r;
}
__device__ __forceinline__ void ffma2(ull& acc, ull a, ull b) {
    asm("fma.rn.f32x2 %0, %1, %2, %0;" : "+l"(acc) : "l"(a), "l"(b));
}
__device__ __forceinline__ float lo32(ull v) {
    return __uint_as_float((unsigned)(v & 0xffffffffull));
}
__device__ __forceinline__ float hi32(ull v) {
    return __uint_as_float((unsigned)(v >> 32));
}
__device__ __forceinline__ float ex2f(float t) {
    float p; asm("ex2.approx.f32 %0, %1;" : "=f"(p) : "f"(t)); return p;
}
__device__ __forceinline__ unsigned flipf(float x) {
    unsigned u = __float_as_uint(x);
    unsigned mask = (unsigned)((int)u >> 31) | 0x80000000u;
    return u ^ mask;
}
__device__ __forceinline__ float unflipf(unsigned u) {
    unsigned mask = (u & 0x80000000u) ? 0x80000000u : 0xffffffffu;
    return __uint_as_float(u ^ mask);
}

#define L2E 1.4426950408889634f
#define C02 0.28853900817779268f   /* 0.2 * log2(e) */

// ---------------------------------------------------------------------------
// Kernel 1: h[h,b,n,k] = sum_d inputs[b,n,d] * linear[h,d,k]
// grid = H*B*4 (128-row segments), 256 threads. Thread = 4 rows x 4 cols.
// xsm padded to 68-float rows: the 4 row-groups/warp hit disjoint banks.
// ---------------------------------------------------------------------------
__global__ void __launch_bounds__(256) proj_kernel(const float* __restrict__ inputs,
                                                   const float* __restrict__ linear) {
    const int blk = blockIdx.x;
    const int hb = blk >> 2;
    const int seg = blk & 3;
    const int h = hb >> 5;
    const int b = hb & 31;

    __shared__ __align__(16) float Wsm[D_IN * D_H];   // 8 KB
    __shared__ __align__(16) float xsm[128 * XST];    // 34 KB

    {
        const float4* W4 = (const float4*)(linear + h * D_IN * D_H);
        float4* Ws4 = (float4*)Wsm;
        for (int i = threadIdx.x; i < D_IN * D_H / 4; i += 256) Ws4[i] = W4[i];
        const float4* x4 = (const float4*)(inputs +
                           ((size_t)b * N_NODES + seg * 128) * D_IN);
        for (int i = threadIdx.x; i < 128 * D_IN / 4; i += 256) {
            int r = i >> 4, d4 = i & 15;
            *(float4*)&xsm[r * XST + d4 * 4] = x4[i];
        }
    }
    __syncthreads();

    const int k4 = threadIdx.x & 7;        // 16B column chunk (4 cols)
    const int r0 = (threadIdx.x >> 3) * 4; // local row base (0..124)

    ull acc[4][2];
#pragma unroll
    for (int ri = 0; ri < 4; ri++) { acc[ri][0] = 0ull; acc[ri][1] = 0ull; }

    const ulonglong2* Wu = (const ulonglong2*)Wsm;

    for (int d0 = 0; d0 < D_IN; d0 += 4) {
        float4 xv[4];
#pragma unroll
        for (int ri = 0; ri < 4; ri++)
            xv[ri] = *(const float4*)&xsm[(r0 + ri) * XST + d0];
#pragma unroll
        for (int dd = 0; dd < 4; dd++) {
            ulonglong2 wv = Wu[(d0 + dd) * 8 + k4];
#pragma unroll
            for (int ri = 0; ri < 4; ri++) {
                ull x2 = pack2(((const float*)&xv[ri])[dd]);
                ffma2(acc[ri][0], wv.x, x2);
                ffma2(acc[ri][1], wv.y, x2);
            }
        }
    }

    float* out = g_h + ((size_t)hb * N_NODES + seg * 128) * D_H;
#pragma unroll
    for (int ri = 0; ri < 4; ri++) {
        float4 v;
        v.x = lo32(acc[ri][0]); v.y = hi32(acc[ri][0]);
        v.z = lo32(acc[ri][1]); v.w = hi32(acc[ri][1]);
        *(float4*)&out[(r0 + ri) * D_H + k4 * 4] = v;
    }
}

// ---------------------------------------------------------------------------
// Kernel 2: attention via branch factorization + sort + balanced rank chunks.
//   p_ij = exp(lrelu(et_i+es_j)) = u_i*v_j (s>0) | u2_i*v2_j (s<0)
// 512 threads (16 warps): halves every per-warp serial loop vs the 256-thread
// version. Sort j by es_j (bitonic); 32 chunks of 16 sorted ranks; exclusive
// scans; per-thread binary search; per-row <=15-element remainder.
// ~88.6 KB smem -> 2 CTA/SM (1024 thr/SM), 1 wave.
// Output overwrites g_h slice in place.
// ---------------------------------------------------------------------------
__global__ void __launch_bounds__(512, 2) att_kernel(const float* __restrict__ att_src,
                                                     const float* __restrict__ att_tar) {
    extern __shared__ float smem[];
    float* hsm  = smem;                        // 512*32 = 16384
    float* uni  = hsm + N_NODES * D_H;
    ull*   keys = (ull*)uni;                   // 512 ull (1024 f)
    float* esrc = uni + 1024;                  // 512
    float* etar = uni + 1536;                  // 512
    float* vs   = uni + 2048;                  // 512 (sorted order)
    float* v2s  = uni + 2560;                  // 512
    int*   tarr = (int*)(uni + 3072);          // 512
    float* Lc1  = uni + 3584;                  // 33*32
    float* Lc2  = Lc1 + (NC + 1) * 32;         // 33*32
    float* cv1  = Lc2 + (NC + 1) * 32;         // 33
    float* cv2  = cv1 + NC + 1;                // 33

    const int hb = blockIdx.x;
    const int h = hb >> 5;
    const int tid = threadIdx.x;
    const int wid = tid >> 5;                  // 0..15
    const int lane = tid & 31;
    const unsigned FULL = 0xffffffffu;

    float* gslice = g_h + (size_t)hb * N_NODES * D_H;

    // ---- load h tile (64 KB) ----
    {
        const float4* src = (const float4*)gslice;
        float4* dst = (float4*)hsm;
        for (int i = tid; i < N_NODES * D_H / 4; i += 512) dst[i] = src[i];
    }
    __syncthreads();

    // ---- e_src / e_tar dot products (warp per row, 32 rows/warp) ----
    {
        const float as = att_src[h * D_H + lane];
        const float at = att_tar[h * D_H + lane];
        for (int j = wid; j < N_NODES; j += 16) {
            float v = hsm[j * D_H + lane];
            float s1 = v * as;
            float s2 = v * at;
#pragma unroll
            for (int off = 16; off; off >>= 1) {
                s1 += __shfl_xor_sync(FULL, s1, off);
                s2 += __shfl_xor_sync(FULL, s2, off);
            }
            if (lane == 0) { esrc[j] = s1; etar[j] = s2; }
        }
    }
    __syncthreads();

    // ---- sort keys by es (asc): key = flip(es) << 32 | j ----
    if (tid < N_NODES)
        keys[tid] = ((ull)flipf(esrc[tid]) << 32) | (unsigned)tid;
    for (int k2 = 2; k2 <= N_NODES; k2 <<= 1) {
        for (int j2 = k2 >> 1; j2 > 0; j2 >>= 1) {
            __syncthreads();
            if (tid < N_NODES) {
                int i = tid;
                int ixj = i ^ j2;
                if (ixj > i) {
                    ull a = keys[i], bb = keys[ixj];
                    if ((a > bb) == ((i & k2) == 0)) { keys[i] = bb; keys[ixj] = a; }
                }
            }
        }
    }
    __syncthreads();

    // ---- vs/v2s at sorted rank + per-thread binary search (1 row each) ----
    if (tid < N_NODES) {
        float e = unflipf((unsigned)(keys[tid] >> 32));
        vs[tid]  = ex2f(e * L2E);
        v2s[tid] = ex2f(e * C02);
    }
    __syncthreads();
    if (tid < N_NODES) {
        ull target = ((ull)flipf(-etar[tid])) << 32;
        int lo = 0, hi = N_NODES;
#pragma unroll
        for (int it = 0; it < 9; it++) {
            int mid = (lo + hi) >> 1;
            if (keys[mid] < target) lo = mid + 1; else hi = mid;
        }
        tarr[tid] = lo;
    }
    __syncthreads();

    // ---- chunk partial sums (32 chunks of 16, 2 chunks/warp: balanced) ----
    for (int c = wid; c < NC; c += 16) {
        float l1 = 0.f, l2 = 0.f;
#pragma unroll 4
        for (int tt = 0; tt < CSZ; tt++) {
            int t = c * CSZ + tt;
            int j = (int)(unsigned)(keys[t] & 0xffffffffull);
            float x = hsm[j * D_H + lane];
            l1 = fmaf(vs[t], x, l1);
            l2 = fmaf(v2s[t], x, l2);
        }
        Lc1[c * 32 + lane] = l1;
        Lc2[c * 32 + lane] = l2;
        // scalar chunk sums: half-warp reductions (lanes 0-15: v, 16-31: v2)
        float sv = (lane < 16) ? vs[c * CSZ + lane] : v2s[c * CSZ + (lane - 16)];
#pragma unroll
        for (int off = 8; off; off >>= 1)
            sv += __shfl_xor_sync(FULL, sv, off);
        if (lane == 0) cv1[c] = sv;
        if (lane == 16) cv2[c] = sv;
    }
    __syncthreads();

    // ---- exclusive scans over chunks ----
    if (wid == 0) {
        float run = 0.f;
#pragma unroll
        for (int c = 0; c < NC; c++) {
            float t = Lc1[c * 32 + lane]; Lc1[c * 32 + lane] = run; run += t;
        }
        Lc1[NC * 32 + lane] = run;
    } else if (wid == 1) {
        float run = 0.f;
#pragma unroll
        for (int c = 0; c < NC; c++) {
            float t = Lc2[c * 32 + lane]; Lc2[c * 32 + lane] = run; run += t;
        }
        Lc2[NC * 32 + lane] = run;
    } else if (wid == 2) {
        float x = cv1[lane];
        float inc = x;
#pragma unroll
        for (int off = 1; off < 32; off <<= 1) {
            float y = __shfl_up_sync(FULL, inc, off);
            if (lane >= off) inc += y;
        }
        cv1[lane] = inc - x;
        if (lane == 31) cv1[NC] = inc;
    } else if (wid == 3) {
        float x = cv2[lane];
        float inc = x;
#pragma unroll
        for (int off = 1; off < 32; off <<= 1) {
            float y = __shfl_up_sync(FULL, inc, off);
            if (lane >= off) inc += y;
        }
        cv2[lane] = inc - x;
        if (lane == 31) cv2[NC] = inc;
    }
    __syncthreads();

    // ---- per-row combine: warp w -> rows [32w, 32w+32) ----
    {
        const float Tv1 = cv1[NC];
        const float T1k = Lc1[NC * 32 + lane];
        for (int r = 0; r < 32; r++) {
            const int i = wid * 32 + r;
            const int t = tarr[i];
            const int c = t >> 4;          // CSZ = 16
            float S1 = Lc1[c * 32 + lane];
            float S2 = Lc2[c * 32 + lane];
            float Sv1 = cv1[c];
            float Sv2 = cv2[c];
            const int t0 = c << 4;
#pragma unroll 4
            for (int tp = t0; tp < t; tp++) {
                int j = (int)(unsigned)(keys[tp] & 0xffffffffull);
                float x = hsm[j * D_H + lane];
                float a = vs[tp], b2 = v2s[tp];
                S1 = fmaf(a, x, S1);
                S2 = fmaf(b2, x, S2);
                Sv1 += a; Sv2 += b2;
            }
            float et = etar[i];
            float es = esrc[i];
            float u  = ex2f(et * L2E);
            float u2 = ex2f(et * C02);
            float s = et + es;
            float ps = ex2f(fmaf(fmaxf(s, 0.f), L2E, fminf(s, 0.f) * C02));
            float denom = u * (Tv1 - Sv1) + u2 * Sv2 - ps;
            float sc = 1.f / denom;
            float hx = hsm[i * D_H + lane];
            gslice[i * D_H + lane] = (u * (T1k - S1) + u2 * S2 - ps * hx) * sc;
        }
    }
}

// ---------------------------------------------------------------------------
// Kernel 3: msgs = tanh(mean_h(head_msgs) + bias); GRU gated update -> out
// grid = B * 8 (64-row chunks), 256 threads. d-outer: W loaded once per d,
// reused across 8 rows.
// ---------------------------------------------------------------------------
__global__ void __launch_bounds__(256) gru_kernel(const float* __restrict__ inputs,
                           const float* __restrict__ hidden,
                           const float* __restrict__ bias,
                           const float* __restrict__ W_hr,
                           const float* __restrict__ W_hi,
                           const float* __restrict__ W_hm,
                           const float* __restrict__ W_ir,
                           const float* __restrict__ b_ir,
                           const float* __restrict__ W_ii,
                           const float* __restrict__ b_ii,
                           const float* __restrict__ W_in,
                           const float* __restrict__ b_in,
                           float* __restrict__ out) {
    extern __shared__ float smem[];
    float* Wir = smem;                    // 2048
    float* Wii = Wir + D_IN * D_H;        // 2048
    float* Win = Wii + D_IN * D_H;        // 2048
    float* Whr = Win + D_IN * D_H;        // 1024
    float* Whi = Whr + D_H * D_H;         // 1024
    float* Whm = Whi + D_H * D_H;         // 1024
    float* xsm = Whm + D_H * D_H;         // 64*64
    float* msm = xsm + 64 * D_IN;         // 64*32

    const int b = blockIdx.x >> 3;
    const int n0 = (blockIdx.x & 7) * 64;

    for (int i = threadIdx.x; i < D_IN * D_H; i += 256) {
        Wir[i] = W_ir[i]; Wii[i] = W_ii[i]; Win[i] = W_in[i];
    }
    for (int i = threadIdx.x; i < D_H * D_H; i += 256) {
        Whr[i] = W_hr[i]; Whi[i] = W_hi[i]; Whm[i] = W_hm[i];
    }
    for (int i = threadIdx.x; i < 64 * D_IN / 4; i += 256)
        ((float4*)xsm)[i] =
            ((const float4*)(inputs + ((size_t)b * N_NODES + n0) * D_IN))[i];

    // mean over heads + bias + tanh
    for (int i = threadIdx.x; i < 64 * D_H / 4; i += 256) {
        float4 acc = make_float4(0.f, 0.f, 0.f, 0.f);
#pragma unroll
        for (int h = 0; h < H_HEADS; h++) {
            const float4* src = (const float4*)(g_h +
                ((size_t)(h * B_SZ + b) * N_NODES + n0) * D_H);
            float4 v = src[i];
            acc.x += v.x; acc.y += v.y; acc.z += v.z; acc.w += v.w;
        }
        int k4 = (i & 7) * 4;
        float4 r;
        r.x = tanhf(acc.x * 0.125f + bias[k4 + 0]);
        r.y = tanhf(acc.y * 0.125f + bias[k4 + 1]);
        r.z = tanhf(acc.z * 0.125f + bias[k4 + 2]);
        r.w = tanhf(acc.w * 0.125f + bias[k4 + 3]);
        ((float4*)msm)[i] = r;
    }
    __syncthreads();

    const int k = threadIdx.x & 31;
    const int r0 = threadIdx.x >> 5;

    float xr[8], xi[8], xn[8];
    {
        const float br = b_ir[k], bi = b_ii[k], bn = b_in[k];
#pragma unroll
        for (int e = 0; e < 8; e++) { xr[e] = br; xi[e] = bi; xn[e] = bn; }
    }
    for (int d = 0; d < D_IN; d++) {
        const float wr = Wir[d * D_H + k];
        const float wi = Wii[d * D_H + k];
        const float wn = Win[d * D_H + k];
#pragma unroll
        for (int e = 0; e < 8; e++) {
            float x = xsm[(r0 + 8 * e) * D_IN + d];
            xr[e] = fmaf(x, wr, xr[e]);
            xi[e] = fmaf(x, wi, xi[e]);
            xn[e] = fmaf(x, wn, xn[e]);
        }
    }
    float hr[8], hi[8], hm[8];
#pragma unroll
    for (int e = 0; e < 8; e++) { hr[e] = 0.f; hi[e] = 0.f; hm[e] = 0.f; }
    for (int d = 0; d < D_H; d++) {
        const float wr = Whr[d * D_H + k];
        const float wi = Whi[d * D_H + k];
        const float wm = Whm[d * D_H + k];
#pragma unroll
        for (int e = 0; e < 8; e++) {
            float mm = msm[(r0 + 8 * e) * D_H + d];
            hr[e] = fmaf(mm, wr, hr[e]);
            hi[e] = fmaf(mm, wi, hi[e]);
            hm[e] = fmaf(mm, wm, hm[e]);
        }
    }
#pragma unroll
    for (int e = 0; e < 8; e++) {
        const int r = r0 + 8 * e;
        float mg = 1.f / (1.f + __expf(-(xr[e] + hr[e])));
        float ig = 1.f / (1.f + __expf(-(xi[e] + hi[e])));
        float nn = tanhf(xn[e] + mg * hm[e]);
        const size_t idx = ((size_t)b * N_NODES + n0 + r) * D_H + k;
        out[idx] = ig * nn + (1.f - ig) * hidden[idx];
    }
}

// ---------------------------------------------------------------------------
// Launch
// ---------------------------------------------------------------------------
extern "C" void kernel_launch(void* const* d_in, const int* in_sizes, int n_in,
                              void* d_out, int out_size) {
    const float* inputs  = (const float*)d_in[0];
    const float* hidden  = (const float*)d_in[1];
    const float* linear  = (const float*)d_in[2];
    const float* bias    = (const float*)d_in[3];
    const float* att_src = (const float*)d_in[4];
    const float* att_tar = (const float*)d_in[5];
    const float* W_hr    = (const float*)d_in[6];
    const float* W_hi    = (const float*)d_in[7];
    const float* W_hm    = (const float*)d_in[8];
    const float* W_ir    = (const float*)d_in[9];
    const float* b_ir    = (const float*)d_in[10];
    const float* W_ii    = (const float*)d_in[11];
    const float* b_ii    = (const float*)d_in[12];
    const float* W_in    = (const float*)d_in[13];
    const float* b_in    = (const float*)d_in[14];
    float* out = (float*)d_out;

    const int att_smem = (16384 + 1024 + 4 * 512 + 512 +
                          2 * (NC + 1) * 32 + 2 * (NC + 1)) * sizeof(float);
    const int gru_smem = (3 * D_IN * D_H + 3 * D_H * D_H + 64 * D_IN + 64 * D_H)
                         * sizeof(float);                          // 61440

    static bool attr_done = false;
    if (!attr_done) {
        cudaFuncSetAttribute(att_kernel, cudaFuncAttributeMaxDynamicSharedMemorySize,
                             att_smem);
        cudaFuncSetAttribute(gru_kernel, cudaFuncAttributeMaxDynamicSharedMemorySize,
                             gru_smem);
        attr_done = true;
    }

    proj_kernel<<<H_HEADS * B_SZ * 4, 256>>>(inputs, linear);
    att_kernel<<<H_HEADS * B_SZ, 512, att_smem>>>(att_src, att_tar);
    gru_kernel<<<B_SZ * 8, 256, gru_smem>>>(inputs, hidden, bias,
                                            W_hr, W_hi, W_hm,
                                            W_ir, b_ir, W_ii, b_ii, W_in, b_in,
                                            out);
}

// round 14
// speedup vs baseline: 1.6759x; 1.0606x over previous
#include <cuda_runtime.h>
#include <cstdint>

#define H_HEADS 8
#define D_IN 64
#define D_H 32
#define B_SZ 32
#define N_NODES 512
#define NC 64                      /* sorted-rank chunks */
#define CSZ 8                      /* chunk size */
#define XST 68                     /* padded xsm row stride (floats) */

typedef unsigned long long ull;

// Scratch: h[h][b][n][k]; attention overwrites each slice in place with the
// per-head aggregated messages; gru averages heads.
__device__ float g_h[H_HEADS * B_SZ * N_NODES * D_H];    // 16 MB

__device__ __forceinline__ ull pack2(float x) {
    ull r; asm("mov.b64 %0, {%1, %1};" : "=l"(r) : "f"(x)); return r;
}
__device__ __forceinline__ void ffma2(ull& acc, ull a, ull b) {
    asm("fma.rn.f32x2 %0, %1, %2, %0;" : "+l"(acc) : "l"(a), "l"(b));
}
__device__ __forceinline__ float lo32(ull v) {
    return __uint_as_float((unsigned)(v & 0xffffffffull));
}
__device__ __forceinline__ float hi32(ull v) {
    return __uint_as_float((unsigned)(v >> 32));
}
__device__ __forceinline__ float ex2f(float t) {
    float p; asm("ex2.approx.f32 %0, %1;" : "=f"(p) : "f"(t)); return p;
}
__device__ __forceinline__ unsigned flipf(float x) {
    unsigned u = __float_as_uint(x);
    unsigned mask = (unsigned)((int)u >> 31) | 0x80000000u;
    return u ^ mask;
}
__device__ __forceinline__ float unflipf(unsigned u) {
    unsigned mask = (u & 0x80000000u) ? 0x80000000u : 0xffffffffu;
    return __uint_as_float(u ^ mask);
}

#define L2E 1.4426950408889634f
#define C02 0.28853900817779268f   /* 0.2 * log2(e) */

// ---------------------------------------------------------------------------
// Kernel 1: h[h,b,n,k] = sum_d inputs[b,n,d] * linear[h,d,k]
// grid = H*B*4 (128-row segments), 256 threads. Thread = 4 rows x 4 cols.
// ---------------------------------------------------------------------------
__global__ void __launch_bounds__(256) proj_kernel(const float* __restrict__ inputs,
                                                   const float* __restrict__ linear) {
    const int blk = blockIdx.x;
    const int hb = blk >> 2;
    const int seg = blk & 3;
    const int h = hb >> 5;
    const int b = hb & 31;

    __shared__ __align__(16) float Wsm[D_IN * D_H];   // 8 KB
    __shared__ __align__(16) float xsm[128 * XST];    // 34 KB

    {
        const float4* W4 = (const float4*)(linear + h * D_IN * D_H);
        float4* Ws4 = (float4*)Wsm;
        for (int i = threadIdx.x; i < D_IN * D_H / 4; i += 256) Ws4[i] = W4[i];
        const float4* x4 = (const float4*)(inputs +
                           ((size_t)b * N_NODES + seg * 128) * D_IN);
        for (int i = threadIdx.x; i < 128 * D_IN / 4; i += 256) {
            int r = i >> 4, d4 = i & 15;
            *(float4*)&xsm[r * XST + d4 * 4] = x4[i];
        }
    }
    __syncthreads();

    const int k4 = threadIdx.x & 7;        // 16B column chunk (4 cols)
    const int r0 = (threadIdx.x >> 3) * 4; // local row base (0..124)

    ull acc[4][2];
#pragma unroll
    for (int ri = 0; ri < 4; ri++) { acc[ri][0] = 0ull; acc[ri][1] = 0ull; }

    const ulonglong2* Wu = (const ulonglong2*)Wsm;

    for (int d0 = 0; d0 < D_IN; d0 += 4) {
        float4 xv[4];
#pragma unroll
        for (int ri = 0; ri < 4; ri++)
            xv[ri] = *(const float4*)&xsm[(r0 + ri) * XST + d0];
#pragma unroll
        for (int dd = 0; dd < 4; dd++) {
            ulonglong2 wv = Wu[(d0 + dd) * 8 + k4];
#pragma unroll
            for (int ri = 0; ri < 4; ri++) {
                ull x2 = pack2(((const float*)&xv[ri])[dd]);
                ffma2(acc[ri][0], wv.x, x2);
                ffma2(acc[ri][1], wv.y, x2);
            }
        }
    }

    float* out = g_h + ((size_t)hb * N_NODES + seg * 128) * D_H;
#pragma unroll
    for (int ri = 0; ri < 4; ri++) {
        float4 v;
        v.x = lo32(acc[ri][0]); v.y = hi32(acc[ri][0]);
        v.z = lo32(acc[ri][1]); v.w = hi32(acc[ri][1]);
        *(float4*)&out[(r0 + ri) * D_H + k4 * 4] = v;
    }
}

// ---------------------------------------------------------------------------
// Kernel 2: attention via branch factorization + sort + balanced rank chunks.
//   p_ij = exp(lrelu(et_i+es_j)) = u_i*v_j (s>0) | u2_i*v2_j (s<0)
// 512 threads. Sort j by es_j (bitonic); pack (v, v2, j) into one float4
// per sorted rank (single LDS.128 broadcast in hot loops); 64 chunks of 8;
// exclusive scans; per-thread binary search; per-row <=7-element remainder.
// ~99 KB smem -> 2 CTA/SM, 1 wave. Output overwrites g_h slice in place.
// ---------------------------------------------------------------------------
__global__ void __launch_bounds__(512, 2) att_kernel(const float* __restrict__ att_src,
                                                     const float* __restrict__ att_tar) {
    extern __shared__ __align__(16) float smem[];
    float* hsm  = smem;                        // 512*32 = 16384
    ull*   keys = (ull*)(hsm + 16384);         // 512 ull (1024 f)
    float4* srt = (float4*)(hsm + 17408);      // 512 float4 (2048 f) {v,v2,j,-}
    float* esrc = hsm + 19456;                 // 512
    float* etar = esrc + 512;                  // 512
    int*   tarr = (int*)(etar + 512);          // 512
    float* Lc1  = (float*)(tarr + 512);        // 65*32 = 2080
    float* Lc2  = Lc1 + (NC + 1) * 32;         // 2080
    float* cv1  = Lc2 + (NC + 1) * 32;         // 65
    float* cv2  = cv1 + NC + 1;                // 65

    const int hb = blockIdx.x;
    const int h = hb >> 5;
    const int tid = threadIdx.x;
    const int wid = tid >> 5;                  // 0..15
    const int lane = tid & 31;
    const unsigned FULL = 0xffffffffu;

    float* gslice = g_h + (size_t)hb * N_NODES * D_H;

    // ---- load h tile (64 KB) ----
    {
        const float4* src = (const float4*)gslice;
        float4* dst = (float4*)hsm;
        for (int i = tid; i < N_NODES * D_H / 4; i += 512) dst[i] = src[i];
    }
    __syncthreads();

    // ---- e_src / e_tar dot products (warp per row, 32 rows/warp) ----
    {
        const float as = att_src[h * D_H + lane];
        const float at = att_tar[h * D_H + lane];
        for (int j = wid; j < N_NODES; j += 16) {
            float v = hsm[j * D_H + lane];
            float s1 = v * as;
            float s2 = v * at;
#pragma unroll
            for (int off = 16; off; off >>= 1) {
                s1 += __shfl_xor_sync(FULL, s1, off);
                s2 += __shfl_xor_sync(FULL, s2, off);
            }
            if (lane == 0) { esrc[j] = s1; etar[j] = s2; }
        }
    }
    __syncthreads();

    // ---- sort keys by es (asc): key = flip(es) << 32 | j ----
    if (tid < N_NODES)
        keys[tid] = ((ull)flipf(esrc[tid]) << 32) | (unsigned)tid;
    for (int k2 = 2; k2 <= N_NODES; k2 <<= 1) {
        for (int j2 = k2 >> 1; j2 > 0; j2 >>= 1) {
            __syncthreads();
            if (tid < N_NODES) {
                int i = tid;
                int ixj = i ^ j2;
                if (ixj > i) {
                    ull a = keys[i], bb = keys[ixj];
                    if ((a > bb) == ((i & k2) == 0)) { keys[i] = bb; keys[ixj] = a; }
                }
            }
        }
    }
    __syncthreads();

    // ---- srt[t] = {v, v2, j} + per-thread binary search (1 row each) ----
    if (tid < N_NODES) {
        ull kk = keys[tid];
        float e = unflipf((unsigned)(kk >> 32));
        float4 q;
        q.x = ex2f(e * L2E);
        q.y = ex2f(e * C02);
        q.z = __int_as_float((int)(unsigned)(kk & 0xffffffffull));
        q.w = 0.f;
        srt[tid] = q;

        ull target = ((ull)flipf(-etar[tid])) << 32;
        int lo = 0, hi = N_NODES;
#pragma unroll
        for (int it = 0; it < 9; it++) {
            int mid = (lo + hi) >> 1;
            if (keys[mid] < target) lo = mid + 1; else hi = mid;
        }
        tarr[tid] = lo;
    }
    __syncthreads();

    // ---- chunk partial sums (64 chunks of 8, 4 chunks/warp) ----
    for (int c = wid; c < NC; c += 16) {
        float l1 = 0.f, l2 = 0.f, sv1 = 0.f, sv2 = 0.f;
#pragma unroll
        for (int tt = 0; tt < CSZ; tt++) {
            float4 q = srt[c * CSZ + tt];
            float x = hsm[__float_as_int(q.z) * D_H + lane];
            l1 = fmaf(q.x, x, l1);
            l2 = fmaf(q.y, x, l2);
            sv1 += q.x; sv2 += q.y;
        }
        Lc1[c * 32 + lane] = l1;
        Lc2[c * 32 + lane] = l2;
        if (lane == 0) { cv1[c] = sv1; cv2[c] = sv2; }
    }
    __syncthreads();

    // ---- exclusive scans over 64 chunks ----
    if (wid == 0) {
        float run = 0.f;
#pragma unroll
        for (int c = 0; c < NC; c++) {
            float t = Lc1[c * 32 + lane]; Lc1[c * 32 + lane] = run; run += t;
        }
        Lc1[NC * 32 + lane] = run;
    } else if (wid == 1) {
        float run = 0.f;
#pragma unroll
        for (int c = 0; c < NC; c++) {
            float t = Lc2[c * 32 + lane]; Lc2[c * 32 + lane] = run; run += t;
        }
        Lc2[NC * 32 + lane] = run;
    } else if (wid == 2 || wid == 3) {
        float* cv = (wid == 2) ? cv1 : cv2;
        float a0 = cv[lane], a1 = cv[32 + lane];
        float s0 = a0, s1 = a1;
#pragma unroll
        for (int off = 1; off < 32; off <<= 1) {
            float t0 = __shfl_up_sync(FULL, s0, off);
            float t1 = __shfl_up_sync(FULL, s1, off);
            if (lane >= off) { s0 += t0; s1 += t1; }
        }
        float tot0 = __shfl_sync(FULL, s0, 31);
        cv[lane] = s0 - a0;
        cv[32 + lane] = tot0 + s1 - a1;
        if (lane == 31) cv[NC] = tot0 + s1;
    }
    __syncthreads();

    // ---- per-row combine: warp w -> rows [32w, 32w+32) ----
    {
        const float Tv1 = cv1[NC];
        const float T1k = Lc1[NC * 32 + lane];
        for (int r = 0; r < 32; r++) {
            const int i = wid * 32 + r;
            const int t = tarr[i];
            const int c = t >> 3;          // CSZ = 8
            float S1 = Lc1[c * 32 + lane];
            float S2 = Lc2[c * 32 + lane];
            float Sv1 = cv1[c];
            float Sv2 = cv2[c];
            const int t0 = c << 3;
#pragma unroll 4
            for (int tp = t0; tp < t; tp++) {
                float4 q = srt[tp];
                float x = hsm[__float_as_int(q.z) * D_H + lane];
                S1 = fmaf(q.x, x, S1);
                S2 = fmaf(q.y, x, S2);
                Sv1 += q.x; Sv2 += q.y;
            }
            float et = etar[i];
            float es = esrc[i];
            float u  = ex2f(et * L2E);
            float u2 = ex2f(et * C02);
            float s = et + es;
            float ps = ex2f(fmaf(fmaxf(s, 0.f), L2E, fminf(s, 0.f) * C02));
            float denom = u * (Tv1 - Sv1) + u2 * Sv2 - ps;
            float sc = 1.f / denom;
            float hx = hsm[i * D_H + lane];
            gslice[i * D_H + lane] = (u * (T1k - S1) + u2 * S2 - ps * hx) * sc;
        }
    }
}

// ---------------------------------------------------------------------------
// Kernel 3: msgs = tanh(mean_h(head_msgs) + bias); GRU gated update -> out
// grid = B * 8 (64-row chunks), 256 threads. d-outer: W loaded once per d,
// reused across 8 rows.
// ---------------------------------------------------------------------------
__global__ void __launch_bounds__(256) gru_kernel(const float* __restrict__ inputs,
                           const float* __restrict__ hidden,
                           const float* __restrict__ bias,
                           const float* __restrict__ W_hr,
                           const float* __restrict__ W_hi,
                           const float* __restrict__ W_hm,
                           const float* __restrict__ W_ir,
                           const float* __restrict__ b_ir,
                           const float* __restrict__ W_ii,
                           const float* __restrict__ b_ii,
                           const float* __restrict__ W_in,
                           const float* __restrict__ b_in,
                           float* __restrict__ out) {
    extern __shared__ float smem[];
    float* Wir = smem;                    // 2048
    float* Wii = Wir + D_IN * D_H;        // 2048
    float* Win = Wii + D_IN * D_H;        // 2048
    float* Whr = Win + D_IN * D_H;        // 1024
    float* Whi = Whr + D_H * D_H;         // 1024
    float* Whm = Whi + D_H * D_H;         // 1024
    float* xsm = Whm + D_H * D_H;         // 64*64
    float* msm = xsm + 64 * D_IN;         // 64*32

    const int b = blockIdx.x >> 3;
    const int n0 = (blockIdx.x & 7) * 64;

    for (int i = threadIdx.x; i < D_IN * D_H; i += 256) {
        Wir[i] = W_ir[i]; Wii[i] = W_ii[i]; Win[i] = W_in[i];
    }
    for (int i = threadIdx.x; i < D_H * D_H; i += 256) {
        Whr[i] = W_hr[i]; Whi[i] = W_hi[i]; Whm[i] = W_hm[i];
    }
    for (int i = threadIdx.x; i < 64 * D_IN / 4; i += 256)
        ((float4*)xsm)[i] =
            ((const float4*)(inputs + ((size_t)b * N_NODES + n0) * D_IN))[i];

    // mean over heads + bias + tanh
    for (int i = threadIdx.x; i < 64 * D_H / 4; i += 256) {
        float4 acc = make_float4(0.f, 0.f, 0.f, 0.f);
#pragma unroll
        for (int h = 0; h < H_HEADS; h++) {
            const float4* src = (const float4*)(g_h +
                ((size_t)(h * B_SZ + b) * N_NODES + n0) * D_H);
            float4 v = src[i];
            acc.x += v.x; acc.y += v.y; acc.z += v.z; acc.w += v.w;
        }
        int k4 = (i & 7) * 4;
        float4 r;
        r.x = tanhf(acc.x * 0.125f + bias[k4 + 0]);
        r.y = tanhf(acc.y * 0.125f + bias[k4 + 1]);
        r.z = tanhf(acc.z * 0.125f + bias[k4 + 2]);
        r.w = tanhf(acc.w * 0.125f + bias[k4 + 3]);
        ((float4*)msm)[i] = r;
    }
    __syncthreads();

    const int k = threadIdx.x & 31;
    const int r0 = threadIdx.x >> 5;

    float xr[8], xi[8], xn[8];
    {
        const float br = b_ir[k], bi = b_ii[k], bn = b_in[k];
#pragma unroll
        for (int e = 0; e < 8; e++) { xr[e] = br; xi[e] = bi; xn[e] = bn; }
    }
    for (int d = 0; d < D_IN; d++) {
        const float wr = Wir[d * D_H + k];
        const float wi = Wii[d * D_H + k];
        const float wn = Win[d * D_H + k];
#pragma unroll
        for (int e = 0; e < 8; e++) {
            float x = xsm[(r0 + 8 * e) * D_IN + d];
            xr[e] = fmaf(x, wr, xr[e]);
            xi[e] = fmaf(x, wi, xi[e]);
            xn[e] = fmaf(x, wn, xn[e]);
        }
    }
    float hr[8], hi[8], hm[8];
#pragma unroll
    for (int e = 0; e < 8; e++) { hr[e] = 0.f; hi[e] = 0.f; hm[e] = 0.f; }
    for (int d = 0; d < D_H; d++) {
        const float wr = Whr[d * D_H + k];
        const float wi = Whi[d * D_H + k];
        const float wm = Whm[d * D_H + k];
#pragma unroll
        for (int e = 0; e < 8; e++) {
            float mm = msm[(r0 + 8 * e) * D_H + d];
            hr[e] = fmaf(mm, wr, hr[e]);
            hi[e] = fmaf(mm, wi, hi[e]);
            hm[e] = fmaf(mm, wm, hm[e]);
        }
    }
#pragma unroll
    for (int e = 0; e < 8; e++) {
        const int r = r0 + 8 * e;
        float mg = 1.f / (1.f + __expf(-(xr[e] + hr[e])));
        float ig = 1.f / (1.f + __expf(-(xi[e] + hi[e])));
        float nn = tanhf(xn[e] + mg * hm[e]);
        const size_t idx = ((size_t)b * N_NODES + n0 + r) * D_H + k;
        out[idx] = ig * nn + (1.f - ig) * hidden[idx];
    }
}

// ---------------------------------------------------------------------------
// Launch
// ---------------------------------------------------------------------------
extern "C" void kernel_launch(void* const* d_in, const int* in_sizes, int n_in,
                              void* d_out, int out_size) {
    const float* inputs  = (const float*)d_in[0];
    const float* hidden  = (const float*)d_in[1];
    const float* linear  = (const float*)d_in[2];
    const float* bias    = (const float*)d_in[3];
    const float* att_src = (const float*)d_in[4];
    const float* att_tar = (const float*)d_in[5];
    const float* W_hr    = (const float*)d_in[6];
    const float* W_hi    = (const float*)d_in[7];
    const float* W_hm    = (const float*)d_in[8];
    const float* W_ir    = (const float*)d_in[9];
    const float* b_ir    = (const float*)d_in[10];
    const float* W_ii    = (const float*)d_in[11];
    const float* b_ii    = (const float*)d_in[12];
    const float* W_in    = (const float*)d_in[13];
    const float* b_in    = (const float*)d_in[14];
    float* out = (float*)d_out;

    // floats: 16384 + 1024 + 2048 + 512 + 512 + 512 + 2*2080 + 2*65
    const int att_smem = (16384 + 1024 + 2048 + 3 * 512 +
                          2 * (NC + 1) * 32 + 2 * (NC + 1)) * sizeof(float);
    const int gru_smem = (3 * D_IN * D_H + 3 * D_H * D_H + 64 * D_IN + 64 * D_H)
                         * sizeof(float);                          // 61440

    static bool attr_done = false;
    if (!attr_done) {
        cudaFuncSetAttribute(att_kernel, cudaFuncAttributeMaxDynamicSharedMemorySize,
                             att_smem);
        cudaFuncSetAttribute(gru_kernel, cudaFuncAttributeMaxDynamicSharedMemorySize,
                             gru_smem);
        attr_done = true;
    }

    proj_kernel<<<H_HEADS * B_SZ * 4, 256>>>(inputs, linear);
    att_kernel<<<H_HEADS * B_SZ, 512, att_smem>>>(att_src, att_tar);
    gru_kernel<<<B_SZ * 8, 256, gru_smem>>>(inputs, hidden, bias,
                                            W_hr, W_hi, W_hm,
                                            W_ir, b_ir, W_ii, b_ii, W_in, b_in,
                                            out);
}

// round 16
// speedup vs baseline: 1.7753x; 1.0593x over previous
#include <cuda_runtime.h>
#include <cstdint>

#define H_HEADS 8
#define D_IN 64
#define D_H 32
#define B_SZ 32
#define N_NODES 512
#define NC 64                      /* sorted-rank chunks */
#define CSZ 8                      /* chunk size */
#define XST 68                     /* padded xsm row stride (floats) */

typedef unsigned long long ull;

// Scratch: h[h][b][n][k]; attention overwrites each slice in place with the
// per-head aggregated messages; gru averages heads.
__device__ float g_h[H_HEADS * B_SZ * N_NODES * D_H];    // 16 MB

__device__ __forceinline__ ull pack2(float x) {
    ull r; asm("mov.b64 %0, {%1, %1};" : "=l"(r) : "f"(x)); return r;
}
__device__ __forceinline__ ull packf(float lo, float hi) {
    ull r; asm("mov.b64 %0, {%1, %2};" : "=l"(r) : "f"(lo), "f"(hi)); return r;
}
__device__ __forceinline__ void ffma2(ull& acc, ull a, ull b) {
    asm("fma.rn.f32x2 %0, %1, %2, %0;" : "+l"(acc) : "l"(a), "l"(b));
}
__device__ __forceinline__ float lo32(ull v) {
    return __uint_as_float((unsigned)(v & 0xffffffffull));
}
__device__ __forceinline__ float hi32(ull v) {
    return __uint_as_float((unsigned)(v >> 32));
}
__device__ __forceinline__ float ex2f(float t) {
    float p; asm("ex2.approx.f32 %0, %1;" : "=f"(p) : "f"(t)); return p;
}
__device__ __forceinline__ unsigned flipf(float x) {
    unsigned u = __float_as_uint(x);
    unsigned mask = (unsigned)((int)u >> 31) | 0x80000000u;
    return u ^ mask;
}
__device__ __forceinline__ float unflipf(unsigned u) {
    unsigned mask = (u & 0x80000000u) ? 0x80000000u : 0xffffffffu;
    return __uint_as_float(u ^ mask);
}

#define L2E 1.4426950408889634f
#define C02 0.28853900817779268f   /* 0.2 * log2(e) */

// ---------------------------------------------------------------------------
// Kernel 1: h[h,b,n,k] = sum_d inputs[b,n,d] * linear[h,d,k]
// grid = H*B*4 (128-row segments), 256 threads. Thread = 4 rows x 4 cols.
// ---------------------------------------------------------------------------
__global__ void __launch_bounds__(256) proj_kernel(const float* __restrict__ inputs,
                                                   const float* __restrict__ linear) {
    const int blk = blockIdx.x;
    const int hb = blk >> 2;
    const int seg = blk & 3;
    const int h = hb >> 5;
    const int b = hb & 31;

    __shared__ __align__(16) float Wsm[D_IN * D_H];   // 8 KB
    __shared__ __align__(16) float xsm[128 * XST];    // 34 KB

    {
        const float4* W4 = (const float4*)(linear + h * D_IN * D_H);
        float4* Ws4 = (float4*)Wsm;
        for (int i = threadIdx.x; i < D_IN * D_H / 4; i += 256) Ws4[i] = W4[i];
        const float4* x4 = (const float4*)(inputs +
                           ((size_t)b * N_NODES + seg * 128) * D_IN);
        for (int i = threadIdx.x; i < 128 * D_IN / 4; i += 256) {
            int r = i >> 4, d4 = i & 15;
            *(float4*)&xsm[r * XST + d4 * 4] = x4[i];
        }
    }
    __syncthreads();

    const int k4 = threadIdx.x & 7;        // 16B column chunk (4 cols)
    const int r0 = (threadIdx.x >> 3) * 4; // local row base (0..124)

    ull acc[4][2];
#pragma unroll
    for (int ri = 0; ri < 4; ri++) { acc[ri][0] = 0ull; acc[ri][1] = 0ull; }

    const ulonglong2* Wu = (const ulonglong2*)Wsm;

    for (int d0 = 0; d0 < D_IN; d0 += 4) {
        float4 xv[4];
#pragma unroll
        for (int ri = 0; ri < 4; ri++)
            xv[ri] = *(const float4*)&xsm[(r0 + ri) * XST + d0];
#pragma unroll
        for (int dd = 0; dd < 4; dd++) {
            ulonglong2 wv = Wu[(d0 + dd) * 8 + k4];
#pragma unroll
            for (int ri = 0; ri < 4; ri++) {
                ull x2 = pack2(((const float*)&xv[ri])[dd]);
                ffma2(acc[ri][0], wv.x, x2);
                ffma2(acc[ri][1], wv.y, x2);
            }
        }
    }

    float* out = g_h + ((size_t)hb * N_NODES + seg * 128) * D_H;
#pragma unroll
    for (int ri = 0; ri < 4; ri++) {
        float4 v;
        v.x = lo32(acc[ri][0]); v.y = hi32(acc[ri][0]);
        v.z = lo32(acc[ri][1]); v.w = hi32(acc[ri][1]);
        *(float4*)&out[(r0 + ri) * D_H + k4 * 4] = v;
    }
}

// ---------------------------------------------------------------------------
// Kernel 2: attention via branch factorization + hybrid sort + rank chunks.
//   p_ij = exp(lrelu(et_i+es_j)) = u_i*v_j (s>0) | u2_i*v2_j (s<0)
// 512 threads. Thread-per-row dot products (no shfl chains) also precompute
// per-row scalars {u, u2, p_self}. Hybrid bitonic sort: keys in registers,
// shfl stages for j2<=16, smem only for j2>=32. 64 chunks of 8 sorted ranks;
// scans; per-thread binary search; <=7-element remainder.
// ~107.5 KB smem -> 2 CTA/SM, 1 wave. Output overwrites g_h slice in place.
// All float4-accessed regions sit at 16B-aligned offsets.
// ---------------------------------------------------------------------------
__global__ void __launch_bounds__(512, 2) att_kernel(const float* __restrict__ att_src,
                                                     const float* __restrict__ att_tar) {
    extern __shared__ __align__(16) float smem[];
    float*  hsm  = smem;                        // [0, 16384)
    float4* srt  = (float4*)(smem + 16384);     // 512 f4: {v, v2, j, -}   (16B ok)
    float4* srow = (float4*)(smem + 18432);     // 512 f4: {u, u2, ps, -}  (16B ok)
    ull*    keys = (ull*)(smem + 20480);        // 512 ull                 (8B ok)
    float*  etar = smem + 21504;                // 512
    int*    tarr = (int*)(smem + 22016);        // 512
    float*  Lc1  = smem + 22528;                // 65*32
    float*  Lc2  = smem + 24608;                // 65*32
    float*  cv1  = smem + 26688;                // 65
    float*  cv2  = smem + 26753;                // 65  (ends 26818)
    float*  asv  = smem + 26820;                // 32  (26820 % 4 == 0 -> 16B ok)
    float*  atv  = smem + 26852;                // 32  (end 26884)

    const int hb = blockIdx.x;
    const int h = hb >> 5;
    const int tid = threadIdx.x;
    const int wid = tid >> 5;                  // 0..15
    const int lane = tid & 31;
    const unsigned FULL = 0xffffffffu;

    float* gslice = g_h + (size_t)hb * N_NODES * D_H;

    // ---- A: load h tile + attention vectors ----
    {
        const float4* src = (const float4*)gslice;
        float4* dst = (float4*)hsm;
        for (int i = tid; i < N_NODES * D_H / 4; i += 512) dst[i] = src[i];
        if (tid < 32) asv[tid] = att_src[h * D_H + tid];
        else if (tid < 64) atv[tid - 32] = att_tar[h * D_H + (tid - 32)];
    }
    __syncthreads();

    // ---- B: thread-per-row dots + per-row scalars + key init ----
    ull kreg;
    {
        const int i = tid;
        const float4* hr = (const float4*)hsm + i * 8;
        const float4* as4 = (const float4*)asv;
        const float4* at4 = (const float4*)atv;
        float es = 0.f, et = 0.f;
#pragma unroll
        for (int q = 0; q < 8; q++) {
            float4 hv = hr[q];
            float4 av = as4[q];
            float4 bv = at4[q];
            es = fmaf(hv.x, av.x, fmaf(hv.y, av.y,
                 fmaf(hv.z, av.z, fmaf(hv.w, av.w, es))));
            et = fmaf(hv.x, bv.x, fmaf(hv.y, bv.y,
                 fmaf(hv.z, bv.z, fmaf(hv.w, bv.w, et))));
        }
        etar[i] = et;
        float4 sr;
        sr.x = ex2f(et * L2E);          // u
        sr.y = ex2f(et * C02);          // u2
        float s = et + es;
        sr.z = ex2f(fmaf(fmaxf(s, 0.f), L2E, fminf(s, 0.f) * C02));  // p_self
        sr.w = 0.f;
        srow[i] = sr;
        kreg = ((ull)flipf(es) << 32) | (unsigned)i;
    }

    // ---- C: hybrid bitonic sort (asc). j2>=32 via smem, j2<=16 via shfl ----
    for (int k2 = 2; k2 <= N_NODES; k2 <<= 1) {
        for (int j2 = k2 >> 1; j2 >= 32; j2 >>= 1) {
            keys[tid] = kreg;
            __syncthreads();
            ull pk = keys[tid ^ j2];
            bool keepmin = ((tid & k2) == 0) == ((tid & j2) == 0);
            kreg = (keepmin == (kreg < pk)) ? kreg : pk;
            __syncthreads();
        }
        int jstart = (k2 >> 1) < 16 ? (k2 >> 1) : 16;
        for (int j2 = jstart; j2 >= 1; j2 >>= 1) {
            ull pk = __shfl_xor_sync(FULL, kreg, j2);
            bool keepmin = ((tid & k2) == 0) == ((tid & j2) == 0);
            kreg = (keepmin == (kreg < pk)) ? kreg : pk;
        }
    }
    keys[tid] = kreg;
    // ---- D: srt pack straight from sorted register ----
    {
        float e = unflipf((unsigned)(kreg >> 32));
        float4 q;
        q.x = ex2f(e * L2E);
        q.y = ex2f(e * C02);
        q.z = __int_as_float((int)(unsigned)(kreg & 0xffffffffull));
        q.w = 0.f;
        srt[tid] = q;
    }
    __syncthreads();

    // ---- E: per-thread binary search + chunk partial sums ----
    {
        ull target = ((ull)flipf(-etar[tid])) << 32;
        int lo = 0, hi = N_NODES;
#pragma unroll
        for (int it = 0; it < 9; it++) {
            int mid = (lo + hi) >> 1;
            if (keys[mid] < target) lo = mid + 1; else hi = mid;
        }
        tarr[tid] = lo;
    }
    for (int c = wid; c < NC; c += 16) {
        float l1 = 0.f, l2 = 0.f, sv1 = 0.f, sv2 = 0.f;
#pragma unroll
        for (int tt = 0; tt < CSZ; tt++) {
            float4 q = srt[c * CSZ + tt];
            float x = hsm[__float_as_int(q.z) * D_H + lane];
            l1 = fmaf(q.x, x, l1);
            l2 = fmaf(q.y, x, l2);
            sv1 += q.x; sv2 += q.y;
        }
        Lc1[c * 32 + lane] = l1;
        Lc2[c * 32 + lane] = l2;
        if (lane == 0) { cv1[c] = sv1; cv2[c] = sv2; }
    }
    __syncthreads();

    // ---- F: exclusive scans over 64 chunks ----
    if (wid == 0) {
        float run = 0.f;
#pragma unroll
        for (int c = 0; c < NC; c++) {
            float t = Lc1[c * 32 + lane]; Lc1[c * 32 + lane] = run; run += t;
        }
        Lc1[NC * 32 + lane] = run;
    } else if (wid == 1) {
        float run = 0.f;
#pragma unroll
        for (int c = 0; c < NC; c++) {
            float t = Lc2[c * 32 + lane]; Lc2[c * 32 + lane] = run; run += t;
        }
        Lc2[NC * 32 + lane] = run;
    } else if (wid == 2 || wid == 3) {
        float* cv = (wid == 2) ? cv1 : cv2;
        float a0 = cv[lane], a1 = cv[32 + lane];
        float s0 = a0, s1 = a1;
#pragma unroll
        for (int off = 1; off < 32; off <<= 1) {
            float t0 = __shfl_up_sync(FULL, s0, off);
            float t1 = __shfl_up_sync(FULL, s1, off);
            if (lane >= off) { s0 += t0; s1 += t1; }
        }
        float tot0 = __shfl_sync(FULL, s0, 31);
        cv[lane] = s0 - a0;
        cv[32 + lane] = tot0 + s1 - a1;
        if (lane == 31) cv[NC] = tot0 + s1;
    }
    __syncthreads();

    // ---- G: per-row combine: warp w -> rows [32w, 32w+32) ----
    {
        const float Tv1 = cv1[NC];
        const float T1k = Lc1[NC * 32 + lane];
        for (int r = 0; r < 32; r++) {
            const int i = wid * 32 + r;
            const int t = tarr[i];
            const int c = t >> 3;          // CSZ = 8
            float4 sr = srow[i];           // {u, u2, ps}
            float S1 = Lc1[c * 32 + lane];
            float S2 = Lc2[c * 32 + lane];
            float Sv1 = cv1[c];
            float Sv2 = cv2[c];
            const int t0 = c << 3;
#pragma unroll 4
            for (int tp = t0; tp < t; tp++) {
                float4 q = srt[tp];
                float x = hsm[__float_as_int(q.z) * D_H + lane];
                S1 = fmaf(q.x, x, S1);
                S2 = fmaf(q.y, x, S2);
                Sv1 += q.x; Sv2 += q.y;
            }
            float denom = sr.x * (Tv1 - Sv1) + sr.y * Sv2 - sr.z;
            float sc = 1.f / denom;
            float hx = hsm[i * D_H + lane];
            gslice[i * D_H + lane] = (sr.x * (T1k - S1) + sr.y * S2 - sr.z * hx) * sc;
        }
    }
}

// ---------------------------------------------------------------------------
// Kernel 3: msgs = tanh(mean_h(head_msgs) + bias); GRU gated update -> out
// grid = B * 8 (64-row chunks), 256 threads. d-outer + f32x2 row pairing:
// fma-pipe warp-instructions halved vs scalar FFMA.
// ---------------------------------------------------------------------------
__global__ void __launch_bounds__(256) gru_kernel(const float* __restrict__ inputs,
                           const float* __restrict__ hidden,
                           const float* __restrict__ bias,
                           const float* __restrict__ W_hr,
                           const float* __restrict__ W_hi,
                           const float* __restrict__ W_hm,
                           const float* __restrict__ W_ir,
                           const float* __restrict__ b_ir,
                           const float* __restrict__ W_ii,
                           const float* __restrict__ b_ii,
                           const float* __restrict__ W_in,
                           const float* __restrict__ b_in,
                           float* __restrict__ out) {
    extern __shared__ float smem[];
    float* Wir = smem;                    // 2048
    float* Wii = Wir + D_IN * D_H;        // 2048
    float* Win = Wii + D_IN * D_H;        // 2048
    float* Whr = Win + D_IN * D_H;        // 1024
    float* Whi = Whr + D_H * D_H;         // 1024
    float* Whm = Whi + D_H * D_H;         // 1024
    float* xsm = Whm + D_H * D_H;         // 64*64
    float* msm = xsm + 64 * D_IN;         // 64*32

    const int b = blockIdx.x >> 3;
    const int n0 = (blockIdx.x & 7) * 64;

    for (int i = threadIdx.x; i < D_IN * D_H; i += 256) {
        Wir[i] = W_ir[i]; Wii[i] = W_ii[i]; Win[i] = W_in[i];
    }
    for (int i = threadIdx.x; i < D_H * D_H; i += 256) {
        Whr[i] = W_hr[i]; Whi[i] = W_hi[i]; Whm[i] = W_hm[i];
    }
    for (int i = threadIdx.x; i < 64 * D_IN / 4; i += 256)
        ((float4*)xsm)[i] =
            ((const float4*)(inputs + ((size_t)b * N_NODES + n0) * D_IN))[i];

    // mean over heads + bias + tanh
    for (int i = threadIdx.x; i < 64 * D_H / 4; i += 256) {
        float4 acc = make_float4(0.f, 0.f, 0.f, 0.f);
#pragma unroll
        for (int h = 0; h < H_HEADS; h++) {
            const float4* src = (const float4*)(g_h +
                ((size_t)(h * B_SZ + b) * N_NODES + n0) * D_H);
            float4 v = src[i];
            acc.x += v.x; acc.y += v.y; acc.z += v.z; acc.w += v.w;
        }
        int k4 = (i & 7) * 4;
        float4 r;
        r.x = tanhf(acc.x * 0.125f + bias[k4 + 0]);
        r.y = tanhf(acc.y * 0.125f + bias[k4 + 1]);
        r.z = tanhf(acc.z * 0.125f + bias[k4 + 2]);
        r.w = tanhf(acc.w * 0.125f + bias[k4 + 3]);
        ((float4*)msm)[i] = r;
    }
    __syncthreads();

    const int k = threadIdx.x & 31;
    const int r0 = threadIdx.x >> 5;

    // pair p: rows (r0 + 8p) [lo] and (r0 + 8(p+4)) [hi]
    ull xr2[4], xi2[4], xn2[4];
    {
        ull brp = pack2(b_ir[k]), bip = pack2(b_ii[k]), bnp = pack2(b_in[k]);
#pragma unroll
        for (int p = 0; p < 4; p++) { xr2[p] = brp; xi2[p] = bip; xn2[p] = bnp; }
    }
    for (int d = 0; d < D_IN; d++) {
        ull wr2 = pack2(Wir[d * D_H + k]);
        ull wi2 = pack2(Wii[d * D_H + k]);
        ull wn2 = pack2(Win[d * D_H + k]);
#pragma unroll
        for (int p = 0; p < 4; p++) {
            float xlo = xsm[(r0 + 8 * p) * D_IN + d];
            float xhi = xsm[(r0 + 8 * (p + 4)) * D_IN + d];
            ull xp = packf(xlo, xhi);
            ffma2(xr2[p], xp, wr2);
            ffma2(xi2[p], xp, wi2);
            ffma2(xn2[p], xp, wn2);
        }
    }
    ull hr2[4], hi2[4], hm2[4];
#pragma unroll
    for (int p = 0; p < 4; p++) { hr2[p] = 0ull; hi2[p] = 0ull; hm2[p] = 0ull; }
    for (int d = 0; d < D_H; d++) {
        ull wr2 = pack2(Whr[d * D_H + k]);
        ull wi2 = pack2(Whi[d * D_H + k]);
        ull wm2 = pack2(Whm[d * D_H + k]);
#pragma unroll
        for (int p = 0; p < 4; p++) {
            float mlo = msm[(r0 + 8 * p) * D_H + d];
            float mhi = msm[(r0 + 8 * (p + 4)) * D_H + d];
            ull mp = packf(mlo, mhi);
            ffma2(hr2[p], mp, wr2);
            ffma2(hi2[p], mp, wi2);
            ffma2(hm2[p], mp, wm2);
        }
    }
#pragma unroll
    for (int p = 0; p < 4; p++) {
#pragma unroll
        for (int half = 0; half < 2; half++) {
            float xrv = half ? hi32(xr2[p]) : lo32(xr2[p]);
            float xiv = half ? hi32(xi2[p]) : lo32(xi2[p]);
            float xnv = half ? hi32(xn2[p]) : lo32(xn2[p]);
            float hrv = half ? hi32(hr2[p]) : lo32(hr2[p]);
            float hiv = half ? hi32(hi2[p]) : lo32(hi2[p]);
            float hmv = half ? hi32(hm2[p]) : lo32(hm2[p]);
            const int r = r0 + 8 * (p + 4 * half);
            float mg = 1.f / (1.f + __expf(-(xrv + hrv)));
            float ig = 1.f / (1.f + __expf(-(xiv + hiv)));
            float nn = tanhf(xnv + mg * hmv);
            const size_t idx = ((size_t)b * N_NODES + n0 + r) * D_H + k;
            out[idx] = ig * nn + (1.f - ig) * hidden[idx];
        }
    }
}

// ---------------------------------------------------------------------------
// Launch
// ---------------------------------------------------------------------------
extern "C" void kernel_launch(void* const* d_in, const int* in_sizes, int n_in,
                              void* d_out, int out_size) {
    const float* inputs  = (const float*)d_in[0];
    const float* hidden  = (const float*)d_in[1];
    const float* linear  = (const float*)d_in[2];
    const float* bias    = (const float*)d_in[3];
    const float* att_src = (const float*)d_in[4];
    const float* att_tar = (const float*)d_in[5];
    const float* W_hr    = (const float*)d_in[6];
    const float* W_hi    = (const float*)d_in[7];
    const float* W_hm    = (const float*)d_in[8];
    const float* W_ir    = (const float*)d_in[9];
    const float* b_ir    = (const float*)d_in[10];
    const float* W_ii    = (const float*)d_in[11];
    const float* b_ii    = (const float*)d_in[12];
    const float* W_in    = (const float*)d_in[13];
    const float* b_in    = (const float*)d_in[14];
    float* out = (float*)d_out;

    const int att_smem = 26884 * sizeof(float);                    // 107536
    const int gru_smem = (3 * D_IN * D_H + 3 * D_H * D_H + 64 * D_IN + 64 * D_H)
                         * sizeof(float);                          // 61440

    static bool attr_done = false;
    if (!attr_done) {
        cudaFuncSetAttribute(att_kernel, cudaFuncAttributeMaxDynamicSharedMemorySize,
                             att_smem);
        cudaFuncSetAttribute(gru_kernel, cudaFuncAttributeMaxDynamicSharedMemorySize,
                             gru_smem);
        attr_done = true;
    }

    proj_kernel<<<H_HEADS * B_SZ * 4, 256>>>(inputs, linear);
    att_kernel<<<H_HEADS * B_SZ, 512, att_smem>>>(att_src, att_tar);
    gru_kernel<<<B_SZ * 8, 256, gru_smem>>>(inputs, hidden, bias,
                                            W_hr, W_hi, W_hm,
                                            W_ir, b_ir, W_ii, b_ii, W_in, b_in,
                                            out);
}

// round 17
// speedup vs baseline: 1.8283x; 1.0298x over previous
#include <cuda_runtime.h>
#include <cstdint>

#define H_HEADS 8
#define D_IN 64
#define D_H 32
#define B_SZ 32
#define N_NODES 512
#define NC 64                      /* sorted-rank chunks */
#define CSZ 8                      /* chunk size */
#define XST 68                     /* padded xsm row stride (floats) */

typedef unsigned long long ull;

// Scratch: h[h][b][n][k]; attention overwrites each slice in place with the
// per-head aggregated messages; gru averages heads.
__device__ float g_h[H_HEADS * B_SZ * N_NODES * D_H];    // 16 MB

__device__ __forceinline__ ull pack2(float x) {
    ull r; asm("mov.b64 %0, {%1, %1};" : "=l"(r) : "f"(x)); return r;
}
__device__ __forceinline__ ull packf(float lo, float hi) {
    ull r; asm("mov.b64 %0, {%1, %2};" : "=l"(r) : "f"(lo), "f"(hi)); return r;
}
__device__ __forceinline__ void ffma2(ull& acc, ull a, ull b) {
    asm("fma.rn.f32x2 %0, %1, %2, %0;" : "+l"(acc) : "l"(a), "l"(b));
}
__device__ __forceinline__ float lo32(ull v) {
    return __uint_as_float((unsigned)(v & 0xffffffffull));
}
__device__ __forceinline__ float hi32(ull v) {
    return __uint_as_float((unsigned)(v >> 32));
}
__device__ __forceinline__ float ex2f(float t) {
    float p; asm("ex2.approx.f32 %0, %1;" : "=f"(p) : "f"(t)); return p;
}
__device__ __forceinline__ unsigned flipf(float x) {
    unsigned u = __float_as_uint(x);
    unsigned mask = (unsigned)((int)u >> 31) | 0x80000000u;
    return u ^ mask;
}
__device__ __forceinline__ float unflipf(unsigned u) {
    unsigned mask = (u & 0x80000000u) ? 0x80000000u : 0xffffffffu;
    return __uint_as_float(u ^ mask);
}

#define L2E 1.4426950408889634f
#define C02 0.28853900817779268f   /* 0.2 * log2(e) */

// ---------------------------------------------------------------------------
// Kernel 1: h[h,b,n,k] = sum_d inputs[b,n,d] * linear[h,d,k]
// grid = H*B*4 (128-row segments), 128 threads. Thread = 4 rows (stride 32)
// x 8 cols. Stride-32 rows: adjacent threads 272B apart == 16 mod 128 ->
// conflict-free float4 x loads. 8 cols doubles W reuse per x-LDS.
// ---------------------------------------------------------------------------
__global__ void __launch_bounds__(128) proj_kernel(const float* __restrict__ inputs,
                                                   const float* __restrict__ linear) {
    const int blk = blockIdx.x;
    const int hb = blk >> 2;
    const int seg = blk & 3;
    const int h = hb >> 5;
    const int b = hb & 31;

    __shared__ __align__(16) float Wsm[D_IN * D_H];   // 8 KB
    __shared__ __align__(16) float xsm[128 * XST];    // 34.8 KB

    {
        const float4* W4 = (const float4*)(linear + h * D_IN * D_H);
        float4* Ws4 = (float4*)Wsm;
        for (int i = threadIdx.x; i < D_IN * D_H / 4; i += 128) Ws4[i] = W4[i];
        const float4* x4 = (const float4*)(inputs +
                           ((size_t)b * N_NODES + seg * 128) * D_IN);
        for (int i = threadIdx.x; i < 128 * D_IN / 4; i += 128) {
            int r = i >> 4, d4 = i & 15;
            *(float4*)&xsm[r * XST + d4 * 4] = x4[i];
        }
    }
    __syncthreads();

    const int k8 = (threadIdx.x & 3) * 8;   // col base (8 cols)
    const int rg = threadIdx.x >> 2;        // 0..31; rows rg + 32*ri

    ull acc[4][4];
#pragma unroll
    for (int ri = 0; ri < 4; ri++)
#pragma unroll
        for (int q = 0; q < 4; q++) acc[ri][q] = 0ull;

    for (int d0 = 0; d0 < D_IN; d0 += 4) {
        float4 xv[4];
#pragma unroll
        for (int ri = 0; ri < 4; ri++)
            xv[ri] = *(const float4*)&xsm[(rg + 32 * ri) * XST + d0];
#pragma unroll
        for (int dd = 0; dd < 4; dd++) {
            const ulonglong2* wr =
                (const ulonglong2*)&Wsm[(d0 + dd) * D_H + k8];
            ulonglong2 w0 = wr[0];
            ulonglong2 w1 = wr[1];
#pragma unroll
            for (int ri = 0; ri < 4; ri++) {
                ull x2 = pack2(((const float*)&xv[ri])[dd]);
                ffma2(acc[ri][0], w0.x, x2);
                ffma2(acc[ri][1], w0.y, x2);
                ffma2(acc[ri][2], w1.x, x2);
                ffma2(acc[ri][3], w1.y, x2);
            }
        }
    }

    float* out = g_h + ((size_t)hb * N_NODES + seg * 128) * D_H;
#pragma unroll
    for (int ri = 0; ri < 4; ri++) {
        const int r = rg + 32 * ri;
        float4 v0, v1;
        v0.x = lo32(acc[ri][0]); v0.y = hi32(acc[ri][0]);
        v0.z = lo32(acc[ri][1]); v0.w = hi32(acc[ri][1]);
        v1.x = lo32(acc[ri][2]); v1.y = hi32(acc[ri][2]);
        v1.z = lo32(acc[ri][3]); v1.w = hi32(acc[ri][3]);
        *(float4*)&out[r * D_H + k8] = v0;
        *(float4*)&out[r * D_H + k8 + 4] = v1;
    }
}

// ---------------------------------------------------------------------------
// Kernel 2: attention via branch factorization + hybrid sort + rank chunks.
//   p_ij = exp(lrelu(et_i+es_j)) = u_i*v_j (s>0) | u2_i*v2_j (s<0)
// 512 threads. Thread-per-row dots precompute row scalars {u,u2,ps}.
// Hybrid bitonic sort (register keys, shfl for j2<=16). 64 chunks of 8;
// PACKED float2 prefix arrays (Lcp/cvp) halve per-row setup LDS; split scan
// (two 32-halves + parallel fixup) halves the serial scan chain.
// ~107.8 KB smem -> 2 CTA/SM, 1 wave. Output overwrites g_h slice in place.
// ---------------------------------------------------------------------------
__global__ void __launch_bounds__(512, 2) att_kernel(const float* __restrict__ att_src,
                                                     const float* __restrict__ att_tar) {
    extern __shared__ __align__(16) float smem[];
    float*  hsm  = smem;                        // [0, 16384)
    float4* srt  = (float4*)(smem + 16384);     // 512 f4: {v, v2, j, -}
    float4* srow = (float4*)(smem + 18432);     // 512 f4: {u, u2, ps, -}
    ull*    keys = (ull*)(smem + 20480);        // 512 ull
    float*  etar = smem + 21504;                // 512
    int*    tarr = (int*)(smem + 22016);        // 512
    float2* Lcp  = (float2*)(smem + 22528);     // 65*32 f2 (4160 floats)
    float2* cvp  = (float2*)(smem + 26688);     // 65 f2 (130 floats)
    float2* Wmid = (float2*)(smem + 26818);     // 32 f2 (64 floats)
    float*  asv  = smem + 26884;                // 32 (16B aligned)
    float*  atv  = smem + 26916;                // 32 (end 26948)

    const int hb = blockIdx.x;
    const int h = hb >> 5;
    const int tid = threadIdx.x;
    const int wid = tid >> 5;                  // 0..15
    const int lane = tid & 31;
    const unsigned FULL = 0xffffffffu;

    float* gslice = g_h + (size_t)hb * N_NODES * D_H;

    // ---- A: load h tile + attention vectors ----
    {
        const float4* src = (const float4*)gslice;
        float4* dst = (float4*)hsm;
        for (int i = tid; i < N_NODES * D_H / 4; i += 512) dst[i] = src[i];
        if (tid < 32) asv[tid] = att_src[h * D_H + tid];
        else if (tid < 64) atv[tid - 32] = att_tar[h * D_H + (tid - 32)];
    }
    __syncthreads();

    // ---- B: thread-per-row dots + per-row scalars + key init ----
    ull kreg;
    {
        const int i = tid;
        const float4* hr = (const float4*)hsm + i * 8;
        const float4* as4 = (const float4*)asv;
        const float4* at4 = (const float4*)atv;
        float es = 0.f, et = 0.f;
#pragma unroll
        for (int q = 0; q < 8; q++) {
            float4 hv = hr[q];
            float4 av = as4[q];
            float4 bv = at4[q];
            es = fmaf(hv.x, av.x, fmaf(hv.y, av.y,
                 fmaf(hv.z, av.z, fmaf(hv.w, av.w, es))));
            et = fmaf(hv.x, bv.x, fmaf(hv.y, bv.y,
                 fmaf(hv.z, bv.z, fmaf(hv.w, bv.w, et))));
        }
        etar[i] = et;
        float4 sr;
        sr.x = ex2f(et * L2E);          // u
        sr.y = ex2f(et * C02);          // u2
        float s = et + es;
        sr.z = ex2f(fmaf(fmaxf(s, 0.f), L2E, fminf(s, 0.f) * C02));  // p_self
        sr.w = 0.f;
        srow[i] = sr;
        kreg = ((ull)flipf(es) << 32) | (unsigned)i;
    }

    // ---- C: hybrid bitonic sort (asc). j2>=32 via smem, j2<=16 via shfl ----
    for (int k2 = 2; k2 <= N_NODES; k2 <<= 1) {
        for (int j2 = k2 >> 1; j2 >= 32; j2 >>= 1) {
            keys[tid] = kreg;
            __syncthreads();
            ull pk = keys[tid ^ j2];
            bool keepmin = ((tid & k2) == 0) == ((tid & j2) == 0);
            kreg = (keepmin == (kreg < pk)) ? kreg : pk;
            __syncthreads();
        }
        int jstart = (k2 >> 1) < 16 ? (k2 >> 1) : 16;
        for (int j2 = jstart; j2 >= 1; j2 >>= 1) {
            ull pk = __shfl_xor_sync(FULL, kreg, j2);
            bool keepmin = ((tid & k2) == 0) == ((tid & j2) == 0);
            kreg = (keepmin == (kreg < pk)) ? kreg : pk;
        }
    }
    keys[tid] = kreg;
    // ---- D: srt pack straight from sorted register ----
    {
        float e = unflipf((unsigned)(kreg >> 32));
        float4 q;
        q.x = ex2f(e * L2E);
        q.y = ex2f(e * C02);
        q.z = __int_as_float((int)(unsigned)(kreg & 0xffffffffull));
        q.w = 0.f;
        srt[tid] = q;
    }
    __syncthreads();

    // ---- E: per-thread binary search + chunk partial sums (packed) ----
    {
        ull target = ((ull)flipf(-etar[tid])) << 32;
        int lo = 0, hi = N_NODES;
#pragma unroll
        for (int it = 0; it < 9; it++) {
            int mid = (lo + hi) >> 1;
            if (keys[mid] < target) lo = mid + 1; else hi = mid;
        }
        tarr[tid] = lo;
    }
    for (int c = wid; c < NC; c += 16) {
        float l1 = 0.f, l2 = 0.f, sv1 = 0.f, sv2 = 0.f;
#pragma unroll
        for (int tt = 0; tt < CSZ; tt++) {
            float4 q = srt[c * CSZ + tt];
            float x = hsm[__float_as_int(q.z) * D_H + lane];
            l1 = fmaf(q.x, x, l1);
            l2 = fmaf(q.y, x, l2);
            sv1 += q.x; sv2 += q.y;
        }
        Lcp[c * 32 + lane] = make_float2(l1, l2);
        if (lane == 0) cvp[c] = make_float2(sv1, sv2);
    }
    __syncthreads();

    // ---- F1: split exclusive scans ----
    if (wid == 0) {
        // scan chunks 0..31; total -> Wmid
        float2 run = make_float2(0.f, 0.f);
#pragma unroll
        for (int c = 0; c < 32; c++) {
            float2 t = Lcp[c * 32 + lane];
            Lcp[c * 32 + lane] = run;
            run.x += t.x; run.y += t.y;
        }
        Wmid[lane] = run;
    } else if (wid == 1) {
        // scan chunks 32..63 locally (relative); local total -> Lcp[64]
        float2 run = make_float2(0.f, 0.f);
#pragma unroll
        for (int c = 32; c < 64; c++) {
            float2 t = Lcp[c * 32 + lane];
            Lcp[c * 32 + lane] = run;
            run.x += t.x; run.y += t.y;
        }
        Lcp[64 * 32 + lane] = run;
    } else if (wid == 2) {
        // full shfl scan of cvp (2x32 with carry)
        float2 a0 = cvp[lane];
        float2 a1 = cvp[32 + lane];
        float s0x = a0.x, s0y = a0.y, s1x = a1.x, s1y = a1.y;
#pragma unroll
        for (int off = 1; off < 32; off <<= 1) {
            float t0x = __shfl_up_sync(FULL, s0x, off);
            float t0y = __shfl_up_sync(FULL, s0y, off);
            float t1x = __shfl_up_sync(FULL, s1x, off);
            float t1y = __shfl_up_sync(FULL, s1y, off);
            if (lane >= off) { s0x += t0x; s0y += t0y; s1x += t1x; s1y += t1y; }
        }
        float totx = __shfl_sync(FULL, s0x, 31);
        float toty = __shfl_sync(FULL, s0y, 31);
        cvp[lane] = make_float2(s0x - a0.x, s0y - a0.y);
        cvp[32 + lane] = make_float2(totx + s1x - a1.x, toty + s1y - a1.y);
        if (lane == 31) cvp[64] = make_float2(totx + s1x, toty + s1y);
    }
    __syncthreads();

    // ---- F2: fixup — add Wmid to chunks 32..64 (parallel across warps) ----
    for (int c = 32 + wid; c <= 64; c += 16) {
        float2 base = Wmid[lane];
        float2 t = Lcp[c * 32 + lane];
        Lcp[c * 32 + lane] = make_float2(t.x + base.x, t.y + base.y);
    }
    __syncthreads();

    // ---- G: per-row combine: warp w -> rows [32w, 32w+32) ----
    {
        const float2 TvP = cvp[NC];
        const float2 T1P = Lcp[NC * 32 + lane];
        const float Tv1 = TvP.x;
        const float T1k = T1P.x;
#pragma unroll 2
        for (int r = 0; r < 32; r++) {
            const int i = wid * 32 + r;
            const int t = tarr[i];
            const int c = t >> 3;          // CSZ = 8
            float4 sr = srow[i];           // {u, u2, ps}
            float2 Sp = Lcp[c * 32 + lane];
            float2 Svp = cvp[c];
            float S1 = Sp.x, S2 = Sp.y;
            float Sv1 = Svp.x, Sv2 = Svp.y;
            const int t0 = c << 3;
#pragma unroll 4
            for (int tp = t0; tp < t; tp++) {
                float4 q = srt[tp];
                float x = hsm[__float_as_int(q.z) * D_H + lane];
                S1 = fmaf(q.x, x, S1);
                S2 = fmaf(q.y, x, S2);
                Sv1 += q.x; Sv2 += q.y;
            }
            float denom = sr.x * (Tv1 - Sv1) + sr.y * Sv2 - sr.z;
            float sc = 1.f / denom;
            float hx = hsm[i * D_H + lane];
            gslice[i * D_H + lane] = (sr.x * (T1k - S1) + sr.y * S2 - sr.z * hx) * sc;
        }
    }
}

// ---------------------------------------------------------------------------
// Kernel 3: msgs = tanh(mean_h(head_msgs) + bias); GRU gated update -> out
// grid = B * 8 (64-row chunks), 256 threads. d-outer + f32x2 row pairing.
// ---------------------------------------------------------------------------
__global__ void __launch_bounds__(256) gru_kernel(const float* __restrict__ inputs,
                           const float* __restrict__ hidden,
                           const float* __restrict__ bias,
                           const float* __restrict__ W_hr,
                           const float* __restrict__ W_hi,
                           const float* __restrict__ W_hm,
                           const float* __restrict__ W_ir,
                           const float* __restrict__ b_ir,
                           const float* __restrict__ W_ii,
                           const float* __restrict__ b_ii,
                           const float* __restrict__ W_in,
                           const float* __restrict__ b_in,
                           float* __restrict__ out) {
    extern __shared__ float smem[];
    float* Wir = smem;                    // 2048
    float* Wii = Wir + D_IN * D_H;        // 2048
    float* Win = Wii + D_IN * D_H;        // 2048
    float* Whr = Win + D_IN * D_H;        // 1024
    float* Whi = Whr + D_H * D_H;         // 1024
    float* Whm = Whi + D_H * D_H;         // 1024
    float* xsm = Whm + D_H * D_H;         // 64*64
    float* msm = xsm + 64 * D_IN;         // 64*32

    const int b = blockIdx.x >> 3;
    const int n0 = (blockIdx.x & 7) * 64;

    for (int i = threadIdx.x; i < D_IN * D_H; i += 256) {
        Wir[i] = W_ir[i]; Wii[i] = W_ii[i]; Win[i] = W_in[i];
    }
    for (int i = threadIdx.x; i < D_H * D_H; i += 256) {
        Whr[i] = W_hr[i]; Whi[i] = W_hi[i]; Whm[i] = W_hm[i];
    }
    for (int i = threadIdx.x; i < 64 * D_IN / 4; i += 256)
        ((float4*)xsm)[i] =
            ((const float4*)(inputs + ((size_t)b * N_NODES + n0) * D_IN))[i];

    // mean over heads + bias + tanh
    for (int i = threadIdx.x; i < 64 * D_H / 4; i += 256) {
        float4 acc = make_float4(0.f, 0.f, 0.f, 0.f);
#pragma unroll
        for (int h = 0; h < H_HEADS; h++) {
            const float4* src = (const float4*)(g_h +
                ((size_t)(h * B_SZ + b) * N_NODES + n0) * D_H);
            float4 v = src[i];
            acc.x += v.x; acc.y += v.y; acc.z += v.z; acc.w += v.w;
        }
        int k4 = (i & 7) * 4;
        float4 r;
        r.x = tanhf(acc.x * 0.125f + bias[k4 + 0]);
        r.y = tanhf(acc.y * 0.125f + bias[k4 + 1]);
        r.z = tanhf(acc.z * 0.125f + bias[k4 + 2]);
        r.w = tanhf(acc.w * 0.125f + bias[k4 + 3]);
        ((float4*)msm)[i] = r;
    }
    __syncthreads();

    const int k = threadIdx.x & 31;
    const int r0 = threadIdx.x >> 5;

    // pair p: rows (r0 + 8p) [lo] and (r0 + 8(p+4)) [hi]
    ull xr2[4], xi2[4], xn2[4];
    {
        ull brp = pack2(b_ir[k]), bip = pack2(b_ii[k]), bnp = pack2(b_in[k]);
#pragma unroll
        for (int p = 0; p < 4; p++) { xr2[p] = brp; xi2[p] = bip; xn2[p] = bnp; }
    }
    for (int d = 0; d < D_IN; d++) {
        ull wr2 = pack2(Wir[d * D_H + k]);
        ull wi2 = pack2(Wii[d * D_H + k]);
        ull wn2 = pack2(Win[d * D_H + k]);
#pragma unroll
        for (int p = 0; p < 4; p++) {
            float xlo = xsm[(r0 + 8 * p) * D_IN + d];
            float xhi = xsm[(r0 + 8 * (p + 4)) * D_IN + d];
            ull xp = packf(xlo, xhi);
            ffma2(xr2[p], xp, wr2);
            ffma2(xi2[p], xp, wi2);
            ffma2(xn2[p], xp, wn2);
        }
    }
    ull hr2[4], hi2[4], hm2[4];
#pragma unroll
    for (int p = 0; p < 4; p++) { hr2[p] = 0ull; hi2[p] = 0ull; hm2[p] = 0ull; }
    for (int d = 0; d < D_H; d++) {
        ull wr2 = pack2(Whr[d * D_H + k]);
        ull wi2 = pack2(Whi[d * D_H + k]);
        ull wm2 = pack2(Whm[d * D_H + k]);
#pragma unroll
        for (int p = 0; p < 4; p++) {
            float mlo = msm[(r0 + 8 * p) * D_H + d];
            float mhi = msm[(r0 + 8 * (p + 4)) * D_H + d];
            ull mp = packf(mlo, mhi);
            ffma2(hr2[p], mp, wr2);
            ffma2(hi2[p], mp, wi2);
            ffma2(hm2[p], mp, wm2);
        }
    }
#pragma unroll
    for (int p = 0; p < 4; p++) {
#pragma unroll
        for (int half = 0; half < 2; half++) {
            float xrv = half ? hi32(xr2[p]) : lo32(xr2[p]);
            float xiv = half ? hi32(xi2[p]) : lo32(xi2[p]);
            float xnv = half ? hi32(xn2[p]) : lo32(xn2[p]);
            float hrv = half ? hi32(hr2[p]) : lo32(hr2[p]);
            float hiv = half ? hi32(hi2[p]) : lo32(hi2[p]);
            float hmv = half ? hi32(hm2[p]) : lo32(hm2[p]);
            const int r = r0 + 8 * (p + 4 * half);
            float mg = 1.f / (1.f + __expf(-(xrv + hrv)));
            float ig = 1.f / (1.f + __expf(-(xiv + hiv)));
            float nn = tanhf(xnv + mg * hmv);
            const size_t idx = ((size_t)b * N_NODES + n0 + r) * D_H + k;
            out[idx] = ig * nn + (1.f - ig) * hidden[idx];
        }
    }
}

// ---------------------------------------------------------------------------
// Launch
// ---------------------------------------------------------------------------
extern "C" void kernel_launch(void* const* d_in, const int* in_sizes, int n_in,
                              void* d_out, int out_size) {
    const float* inputs  = (const float*)d_in[0];
    const float* hidden  = (const float*)d_in[1];
    const float* linear  = (const float*)d_in[2];
    const float* bias    = (const float*)d_in[3];
    const float* att_src = (const float*)d_in[4];
    const float* att_tar = (const float*)d_in[5];
    const float* W_hr    = (const float*)d_in[6];
    const float* W_hi    = (const float*)d_in[7];
    const float* W_hm    = (const float*)d_in[8];
    const float* W_ir    = (const float*)d_in[9];
    const float* b_ir    = (const float*)d_in[10];
    const float* W_ii    = (const float*)d_in[11];
    const float* b_ii    = (const float*)d_in[12];
    const float* W_in    = (const float*)d_in[13];
    const float* b_in    = (const float*)d_in[14];
    float* out = (float*)d_out;

    const int att_smem = 26948 * sizeof(float);                    // 107792
    const int gru_smem = (3 * D_IN * D_H + 3 * D_H * D_H + 64 * D_IN + 64 * D_H)
                         * sizeof(float);                          // 61440

    static bool attr_done = false;
    if (!attr_done) {
        cudaFuncSetAttribute(att_kernel, cudaFuncAttributeMaxDynamicSharedMemorySize,
                             att_smem);
        cudaFuncSetAttribute(gru_kernel, cudaFuncAttributeMaxDynamicSharedMemorySize,
                             gru_smem);
        attr_done = true;
    }

    proj_kernel<<<H_HEADS * B_SZ * 4, 128>>>(inputs, linear);
    att_kernel<<<H_HEADS * B_SZ, 512, att_smem>>>(att_src, att_tar);
    gru_kernel<<<B_SZ * 8, 256, gru_smem>>>(inputs, hidden, bias,
                                            W_hr, W_hi, W_hm,
                                            W_ir, b_ir, W_ii, b_ii, W_in, b_in,
                                            out);
}